// round 10
// baseline (speedup 1.0000x reference)
#include <cuda_runtime.h>
#include <cuda_fp16.h>
#include <math.h>
#include <stdint.h>

// ---------------------------------------------------------------------------
// SmallTransformerBlock via mma.sync fp16 asymmetric-split GEMMs (sm_103 PTX).
// C = A16 @ (Bh + Bl)^T : A fp16, B split hi+lo fp16, 2 MMA passes.
// R10: intra-stage fragment double-buffering (ldsm for ks+1 issued before
// mma for ks -> LDS latency hidden under the mma batch). occ 2.
// ---------------------------------------------------------------------------

#define D_MODEL 1024
#define FF_DIM  4096
#define BATCH   4
#define SEQ     2048
#define M_TOT   (BATCH * SEQ)          // 8192

#define BM 128
#define BN 64
#define BK 64
#define STAGES 2
#define ABUF_BYTES (128 * 128)                 // A: 128 rows x 128B (64 fp16)
#define BBUF_BYTES (64 * 128)                  // Bh: 64 rows x 128B; Bl same
#define STAGE_BYTES (ABUF_BYTES + 2 * BBUF_BYTES)   // 32768
#define SMEM_TOTAL  (STAGES * STAGE_BYTES)          // 65536

typedef __half h16;

// -------------------------- scratch (device globals) -----------------------
__device__ h16   g_x16  [M_TOT * D_MODEL];
__device__ h16   g_wqT_h[D_MODEL * D_MODEL];
__device__ h16   g_wqT_l[D_MODEL * D_MODEL];
__device__ h16   g_wkT_h[D_MODEL * D_MODEL];
__device__ h16   g_wkT_l[D_MODEL * D_MODEL];
__device__ h16   g_wvT_h[D_MODEL * D_MODEL];
__device__ h16   g_wvT_l[D_MODEL * D_MODEL];
__device__ h16   g_woT_h[D_MODEL * D_MODEL];
__device__ h16   g_woT_l[D_MODEL * D_MODEL];
__device__ h16   g_w1T_h[FF_DIM * D_MODEL];
__device__ h16   g_w1T_l[FF_DIM * D_MODEL];
__device__ h16   g_w2T_h[D_MODEL * FF_DIM];
__device__ h16   g_w2T_l[D_MODEL * FF_DIM];
__device__ h16   g_q16  [M_TOT * D_MODEL];
__device__ h16   g_k_h  [M_TOT * D_MODEL];
__device__ h16   g_k_l  [M_TOT * D_MODEL];
__device__ float g_v    [M_TOT * D_MODEL];
__device__ h16   g_vT_h [M_TOT * D_MODEL];     // [B][D,T]
__device__ h16   g_vT_l [M_TOT * D_MODEL];
__device__ float g_s    [BATCH * SEQ * SEQ];
__device__ h16   g_p16  [BATCH * SEQ * SEQ];
__device__ h16   g_ctx16[M_TOT * D_MODEL];
__device__ float g_x1   [M_TOT * D_MODEL];
__device__ float g_y1   [M_TOT * D_MODEL];
__device__ h16   g_y116 [M_TOT * D_MODEL];
__device__ h16   g_h16a [M_TOT * FF_DIM];
__device__ float g_x2   [M_TOT * D_MODEL];

// ------------------------------- PTX helpers -------------------------------
__device__ __forceinline__ uint32_t smem_u32(const void* p) {
    uint32_t a;
    asm("{ .reg .u64 t; cvta.to.shared.u64 t, %1; cvt.u32.u64 %0, t; }"
        : "=r"(a) : "l"(p));
    return a;
}
__device__ __forceinline__ void cp16(uint32_t dst, const void* src) {
    asm volatile("cp.async.cg.shared.global [%0], [%1], 16;\n" :: "r"(dst), "l"(src));
}
__device__ __forceinline__ void cp_commit() {
    asm volatile("cp.async.commit_group;\n" ::: "memory");
}
template<int N> __device__ __forceinline__ void cp_wait() {
    asm volatile("cp.async.wait_group %0;\n" :: "n"(N) : "memory");
}
__device__ __forceinline__ void ldsm4(uint32_t& r0, uint32_t& r1, uint32_t& r2,
                                      uint32_t& r3, uint32_t addr) {
    asm volatile("ldmatrix.sync.aligned.m8n8.x4.shared.b16 {%0,%1,%2,%3}, [%4];\n"
                 : "=r"(r0), "=r"(r1), "=r"(r2), "=r"(r3) : "r"(addr));
}
__device__ __forceinline__ void mma16816(float* d, const uint32_t* a, const uint32_t* b) {
    asm volatile(
        "mma.sync.aligned.m16n8k16.row.col.f32.f16.f16.f32 "
        "{%0,%1,%2,%3}, {%4,%5,%6,%7}, {%8,%9}, {%0,%1,%2,%3};\n"
        : "+f"(d[0]), "+f"(d[1]), "+f"(d[2]), "+f"(d[3])
        : "r"(a[0]), "r"(a[1]), "r"(a[2]), "r"(a[3]), "r"(b[0]), "r"(b[1]));
}
__device__ __forceinline__ void split1h(float v, h16& h, h16& l) {
    h = __float2half_rn(v);
    l = __float2half_rn(v - __half2float(h));
}
__device__ __forceinline__ uint32_t pack2h(h16 a, h16 b) {
    return ((uint32_t)__half_as_ushort(b) << 16) | __half_as_ushort(a);
}

// ---------------------------------------------------------------------------
// GEMM NT fp16 2-pass: C[M,N] = A16 @ (Bh+Bl)^T (+bias)(relu)(+res)
// 128x64x64 tile, 8 warps (warp tile 32x32), 2-stage cp.async,
// fragment double-buffered ks loop, 2 CTAs/SM.
// ---------------------------------------------------------------------------
template<bool F32OUT, bool HALFOUT, bool SPLITOUT, bool RELU, bool HASRES>
__global__ __launch_bounds__(256, 2) void gemm_nt(
    const h16* __restrict__ A16,
    const h16* __restrict__ Bhi, const h16* __restrict__ Blo,
    const float* __restrict__ bias, const float* __restrict__ Res,
    float* __restrict__ Cf, h16* __restrict__ Ch,
    h16* __restrict__ Chi, h16* __restrict__ Clo,
    int M, int N, int K, long long aS, long long bS, long long cS)
{
    extern __shared__ char smraw[];
    const uint32_t smb = smem_u32(smraw);
    const int tid  = threadIdx.x;
    const int wid  = tid >> 5;
    const int lane = tid & 31;
    const int wm = wid & 3;            // m offset wm*32
    const int wn = wid >> 2;           // n offset wn*32
    const int quad = lane >> 3, lrow = lane & 7;
    const int bz = blockIdx.z;
    const int bm = blockIdx.y * BM;
    const int bn = blockIdx.x * BN;

    // ---- hoisted global load pointers ----
    const int trow = tid >> 3;                 // 0..31
    const int lc   = tid & 7;                  // 16B chunk 0..7
    const int lk   = lc * 8;                   // k element offset
    const long long rowStep = 32LL * K;        // 32 rows, in elements
    const h16* pA  = A16 + (long long)bz * aS + (long long)(bm + trow) * K + lk;
    const h16* pBh = Bhi + (long long)bz * bS + (long long)(bn + trow) * K + lk;
    const h16* pBl = Blo + (long long)bz * bS + (long long)(bn + trow) * K + lk;
    const uint32_t d0 = (uint32_t)(trow * 128 + ((lc ^ (trow & 7)) * 16));

    // ---- hoisted ldsm base addresses ----
    // addr = stage + base[target] + (((2ks) ^ (lrow&6)) << 4)
    const uint32_t bit4  = (uint32_t)(((quad >> 1) ^ (lrow & 1)) << 4);
    const uint32_t lrow6 = (uint32_t)(lrow & 6);
    uint32_t baseA[2], baseBh[2], baseBl[2];
    #pragma unroll
    for (int fm = 0; fm < 2; fm++)
        baseA[fm] = (uint32_t)((wm * 32 + fm * 16 + (quad & 1) * 8 + lrow) * 128) + bit4;
    #pragma unroll
    for (int f2 = 0; f2 < 2; f2++) {
        uint32_t r = (uint32_t)((wn * 32 + f2 * 16 + (quad & 1) * 8 + lrow) * 128);
        baseBh[f2] = ABUF_BYTES + r + bit4;
        baseBl[f2] = ABUF_BYTES + BBUF_BYTES + r + bit4;
    }

    float acc[2][4][4];
    #pragma unroll
    for (int i = 0; i < 2; i++)
        #pragma unroll
        for (int j = 0; j < 4; j++)
            #pragma unroll
            for (int c = 0; c < 4; c++) acc[i][j][c] = 0.0f;

    const int T = K / BK;

    auto load_stage = [&](int kt, int s) {
        const uint32_t stb = smb + (uint32_t)s * STAGE_BYTES;
        const int k0 = kt * BK;
        cp16(stb + d0,          pA + k0);
        cp16(stb + d0 + 4096,   pA + rowStep + k0);
        cp16(stb + d0 + 8192,   pA + 2 * rowStep + k0);
        cp16(stb + d0 + 12288,  pA + 3 * rowStep + k0);
        cp16(stb + ABUF_BYTES + d0,          pBh + k0);
        cp16(stb + ABUF_BYTES + d0 + 4096,   pBh + rowStep + k0);
        cp16(stb + ABUF_BYTES + BBUF_BYTES + d0,        pBl + k0);
        cp16(stb + ABUF_BYTES + BBUF_BYTES + d0 + 4096, pBl + rowStep + k0);
    };

    // fragment load for one ks group
    auto ld_frags = [&](uint32_t stb, int ks,
                        uint32_t (&ah)[2][4], uint32_t (&bh)[4][2], uint32_t (&bl)[4][2]) {
        const uint32_t kk = ((uint32_t)(ks * 2) ^ lrow6) << 4;
        #pragma unroll
        for (int fm = 0; fm < 2; fm++)
            ldsm4(ah[fm][0], ah[fm][1], ah[fm][2], ah[fm][3], stb + baseA[fm] + kk);
        #pragma unroll
        for (int f2 = 0; f2 < 2; f2++) {
            uint32_t t0, t1, t2, t3;
            ldsm4(t0, t1, t2, t3, stb + baseBh[f2] + kk);
            bh[2*f2][0] = t0; bh[2*f2][1] = t2;
            bh[2*f2+1][0] = t1; bh[2*f2+1][1] = t3;
            ldsm4(t0, t1, t2, t3, stb + baseBl[f2] + kk);
            bl[2*f2][0] = t0; bl[2*f2][1] = t2;
            bl[2*f2+1][0] = t1; bl[2*f2+1][1] = t3;
        }
    };

    auto compute_stage = [&](int s) {
        const uint32_t stb = smb + (uint32_t)s * STAGE_BYTES;
        uint32_t ah[2][2][4], bh[2][4][2], bl[2][4][2];
        ld_frags(stb, 0, ah[0], bh[0], bl[0]);
        #pragma unroll
        for (int ks = 0; ks < 4; ks++) {
            const int cur = ks & 1, nxt = cur ^ 1;
            if (ks < 3) ld_frags(stb, ks + 1, ah[nxt], bh[nxt], bl[nxt]);
            #pragma unroll
            for (int fm = 0; fm < 2; fm++)
                #pragma unroll
                for (int fn = 0; fn < 4; fn++) {
                    float* d = acc[fm][fn];
                    mma16816(d, ah[cur][fm], bh[cur][fn]);
                    mma16816(d, ah[cur][fm], bl[cur][fn]);
                }
        }
    };

    load_stage(0, 0); cp_commit();
    load_stage(1, 1); cp_commit();

    for (int t = 0; t < T; t++) {
        if (t < T - 1) cp_wait<1>(); else cp_wait<0>();
        __syncthreads();
        compute_stage(t & 1);
        if (t < T - 2) {
            __syncthreads();
            load_stage(t + 2, t & 1); cp_commit();
        }
    }

    // ---------------- epilogue ----------------
    const int groupID = lane >> 2, tIdx = lane & 3;
    #pragma unroll
    for (int fm = 0; fm < 2; fm++) {
        #pragma unroll
        for (int half = 0; half < 2; half++) {
            int row = bm + wm * 32 + fm * 16 + half * 8 + groupID;
            long long rbase = (long long)bz * cS + (long long)row * N;
            #pragma unroll
            for (int fn = 0; fn < 4; fn++) {
                int col = bn + wn * 32 + fn * 8 + tIdx * 2;
                float v0 = acc[fm][fn][half * 2 + 0];
                float v1 = acc[fm][fn][half * 2 + 1];
                if (bias) { v0 += __ldg(bias + col); v1 += __ldg(bias + col + 1); }
                if (RELU) { v0 = fmaxf(v0, 0.0f); v1 = fmaxf(v1, 0.0f); }
                if (HASRES) {
                    float2 rv = *(const float2*)(Res + rbase + col);
                    v0 += rv.x; v1 += rv.y;
                }
                if (F32OUT)
                    *(float2*)(Cf + rbase + col) = make_float2(v0, v1);
                if (HALFOUT)
                    *(uint32_t*)(Ch + rbase + col) =
                        pack2h(__float2half_rn(v0), __float2half_rn(v1));
                if (SPLITOUT) {
                    h16 h0, l0, h1, l1;
                    split1h(v0, h0, l0); split1h(v1, h1, l1);
                    *(uint32_t*)(Chi + rbase + col) = pack2h(h0, h1);
                    *(uint32_t*)(Clo + rbase + col) = pack2h(l0, l1);
                }
            }
        }
    }
}

// ---------------------------------------------------------------------------
// Elementwise quantize: fp32 -> fp16
// ---------------------------------------------------------------------------
__global__ __launch_bounds__(256) void quant_kernel(
    const float* __restrict__ src, h16* __restrict__ dst, int n4)
{
    int i = blockIdx.x * 256 + threadIdx.x;
    if (i >= n4) return;
    float4 v = ((const float4*)src)[i];
    ((uint2*)dst)[i] = make_uint2(
        pack2h(__float2half_rn(v.x), __float2half_rn(v.y)),
        pack2h(__float2half_rn(v.z), __float2half_rn(v.w)));
}

// ---------------------------------------------------------------------------
// Transpose-split: src [R,C] fp32 -> dst [C,R] (hi, lo) fp16.
// ---------------------------------------------------------------------------
__global__ __launch_bounds__(256) void transpose_split_kernel(
    const float* __restrict__ src, h16* __restrict__ hiT, h16* __restrict__ loT,
    int R, int C, long long sS, long long dS)
{
    __shared__ float tile[32][33];
    const float* S = src + (long long)blockIdx.z * sS;
    int c0 = blockIdx.x * 32, r0 = blockIdx.y * 32;
    int tx = threadIdx.x & 31, ty = threadIdx.x >> 5;   // 32 x 8
    #pragma unroll
    for (int i = 0; i < 32; i += 8)
        tile[ty + i][tx] = S[(long long)(r0 + ty + i) * C + c0 + tx];
    __syncthreads();
    #pragma unroll
    for (int i = 0; i < 32; i += 8) {
        float v = tile[tx][ty + i];
        h16 h, l; split1h(v, h, l);
        long long o = (long long)blockIdx.z * dS + (long long)(c0 + ty + i) * R + r0 + tx;
        hiT[o] = h; loT[o] = l;
    }
}

// Batched version for the four 1024x1024 weights: z picks the weight.
__global__ __launch_bounds__(256) void transpose_split4_kernel(
    const float* __restrict__ s0, const float* __restrict__ s1,
    const float* __restrict__ s2, const float* __restrict__ s3,
    h16* __restrict__ h0, h16* __restrict__ l0,
    h16* __restrict__ h1, h16* __restrict__ l1,
    h16* __restrict__ h2, h16* __restrict__ l2,
    h16* __restrict__ h3, h16* __restrict__ l3)
{
    __shared__ float tile[32][33];
    const int z = blockIdx.z;
    const float* S = (z == 0) ? s0 : (z == 1) ? s1 : (z == 2) ? s2 : s3;
    h16* H = (z == 0) ? h0 : (z == 1) ? h1 : (z == 2) ? h2 : h3;
    h16* L = (z == 0) ? l0 : (z == 1) ? l1 : (z == 2) ? l2 : l3;
    int c0 = blockIdx.x * 32, r0 = blockIdx.y * 32;
    int tx = threadIdx.x & 31, ty = threadIdx.x >> 5;
    #pragma unroll
    for (int i = 0; i < 32; i += 8)
        tile[ty + i][tx] = S[(long long)(r0 + ty + i) * D_MODEL + c0 + tx];
    __syncthreads();
    #pragma unroll
    for (int i = 0; i < 32; i += 8) {
        float v = tile[tx][ty + i];
        h16 h, l; split1h(v, h, l);
        long long o = (long long)(c0 + ty + i) * D_MODEL + r0 + tx;
        H[o] = h; L[o] = l;
    }
}

// ------------------------------- reductions --------------------------------
__device__ __forceinline__ float block_sum(float v) {
    __shared__ float sh[8];
    int lane = threadIdx.x & 31, w = threadIdx.x >> 5;
    #pragma unroll
    for (int o = 16; o > 0; o >>= 1) v += __shfl_xor_sync(0xffffffffu, v, o);
    if (lane == 0) sh[w] = v;
    __syncthreads();
    if (w == 0) {
        float t = (lane < 8) ? sh[lane] : 0.0f;
        #pragma unroll
        for (int o = 4; o > 0; o >>= 1) t += __shfl_xor_sync(0xffffffffu, t, o);
        if (lane == 0) sh[0] = t;
    }
    __syncthreads();
    float r = sh[0];
    __syncthreads();
    return r;
}
__device__ __forceinline__ float block_max(float v) {
    __shared__ float sh[8];
    int lane = threadIdx.x & 31, w = threadIdx.x >> 5;
    #pragma unroll
    for (int o = 16; o > 0; o >>= 1) v = fmaxf(v, __shfl_xor_sync(0xffffffffu, v, o));
    if (lane == 0) sh[w] = v;
    __syncthreads();
    if (w == 0) {
        float t = (lane < 8) ? sh[lane] : -3.4e38f;
        #pragma unroll
        for (int o = 4; o > 0; o >>= 1) t = fmaxf(t, __shfl_xor_sync(0xffffffffu, t, o));
        if (lane == 0) sh[0] = t;
    }
    __syncthreads();
    float r = sh[0];
    __syncthreads();
    return r;
}

// ---------------------------------------------------------------------------
// Softmax over SEQ=2048 with fused 1/scale; fp16 output.
// ---------------------------------------------------------------------------
__global__ __launch_bounds__(256) void softmax_kernel(
    const float* __restrict__ S, h16* __restrict__ P)
{
    const float inv_scale = 0.0883883476483184f;  // 1/sqrt(128)
    const float* row = S + (long long)blockIdx.x * SEQ;
    int tid = threadIdx.x;

    float4 a = ((const float4*)row)[tid];
    float4 b = ((const float4*)row)[tid + 256];
    a.x*=inv_scale; a.y*=inv_scale; a.z*=inv_scale; a.w*=inv_scale;
    b.x*=inv_scale; b.y*=inv_scale; b.z*=inv_scale; b.w*=inv_scale;

    float m = fmaxf(fmaxf(fmaxf(a.x,a.y), fmaxf(a.z,a.w)),
                    fmaxf(fmaxf(b.x,b.y), fmaxf(b.z,b.w)));
    m = block_max(m);
    a.x=expf(a.x-m); a.y=expf(a.y-m); a.z=expf(a.z-m); a.w=expf(a.w-m);
    b.x=expf(b.x-m); b.y=expf(b.y-m); b.z=expf(b.z-m); b.w=expf(b.w-m);
    float s = a.x+a.y+a.z+a.w + b.x+b.y+b.z+b.w;
    s = block_sum(s);
    float inv = 1.0f / s;
    a.x*=inv; a.y*=inv; a.z*=inv; a.w*=inv;
    b.x*=inv; b.y*=inv; b.z*=inv; b.w*=inv;

    long long base = (long long)blockIdx.x * SEQ;
    ((uint2*)(P + base))[tid] = make_uint2(
        pack2h(__float2half_rn(a.x), __float2half_rn(a.y)),
        pack2h(__float2half_rn(a.z), __float2half_rn(a.w)));
    ((uint2*)(P + base))[tid + 256] = make_uint2(
        pack2h(__float2half_rn(b.x), __float2half_rn(b.y)),
        pack2h(__float2half_rn(b.z), __float2half_rn(b.w)));
}

// ---------------------------------------------------------------------------
// LayerNorm D=1024; optional fp16 quantized emission.
// ---------------------------------------------------------------------------
template<bool EMITH>
__global__ __launch_bounds__(256) void layernorm_kernel(
    const float* __restrict__ X, const float* __restrict__ g,
    const float* __restrict__ b, float* __restrict__ Y, h16* __restrict__ Yh)
{
    const float* x = X + (long long)blockIdx.x * D_MODEL;
    int tid = threadIdx.x;
    float4 v = ((const float4*)x)[tid];
    float s = v.x + v.y + v.z + v.w;
    s = block_sum(s);
    float mean = s * (1.0f / D_MODEL);
    float dx=v.x-mean, dy=v.y-mean, dz=v.z-mean, dw=v.w-mean;
    float ss = dx*dx + dy*dy + dz*dz + dw*dw;
    ss = block_sum(ss);
    float rstd = rsqrtf(ss * (1.0f / D_MODEL) + 1e-5f);
    float4 gg = ((const float4*)g)[tid];
    float4 bb = ((const float4*)b)[tid];
    float4 o;
    o.x = dx*rstd*gg.x + bb.x;
    o.y = dy*rstd*gg.y + bb.y;
    o.z = dz*rstd*gg.z + bb.z;
    o.w = dw*rstd*gg.w + bb.w;
    long long base = (long long)blockIdx.x * D_MODEL;
    ((float4*)(Y + base))[tid] = o;
    if (EMITH) {
        ((uint2*)(Yh + base))[tid] = make_uint2(
            pack2h(__float2half_rn(o.x), __float2half_rn(o.y)),
            pack2h(__float2half_rn(o.z), __float2half_rn(o.w)));
    }
}

// ---------------------------------------------------------------------------
// Launch
// ---------------------------------------------------------------------------
extern "C" void kernel_launch(void* const* d_in, const int* in_sizes, int n_in,
                              void* d_out, int out_size)
{
    const float* x     = (const float*)d_in[0];
    const float* wq    = (const float*)d_in[1];
    const float* bq    = (const float*)d_in[2];
    const float* wk    = (const float*)d_in[3];
    const float* bk    = (const float*)d_in[4];
    const float* wv    = (const float*)d_in[5];
    const float* bv    = (const float*)d_in[6];
    const float* wo    = (const float*)d_in[7];
    const float* bo    = (const float*)d_in[8];
    const float* w1    = (const float*)d_in[9];
    const float* b1    = (const float*)d_in[10];
    const float* w2    = (const float*)d_in[11];
    const float* b2    = (const float*)d_in[12];
    const float* g1    = (const float*)d_in[13];
    const float* beta1 = (const float*)d_in[14];
    const float* g2    = (const float*)d_in[15];
    const float* beta2 = (const float*)d_in[16];
    float* out = (float*)d_out;

    #define SYM(p, s) void* p##_; cudaGetSymbolAddress(&p##_, s);
    SYM(x16, g_x16)
    SYM(wqh, g_wqT_h) SYM(wql, g_wqT_l)
    SYM(wkh, g_wkT_h) SYM(wkl, g_wkT_l)
    SYM(wvh, g_wvT_h) SYM(wvl, g_wvT_l)
    SYM(woh, g_woT_h) SYM(wol, g_woT_l)
    SYM(w1h, g_w1T_h) SYM(w1l, g_w1T_l)
    SYM(w2h, g_w2T_h) SYM(w2l, g_w2T_l)
    SYM(q16, g_q16)  SYM(kh, g_k_h)  SYM(kl, g_k_l)
    SYM(vv, g_v)     SYM(vth, g_vT_h) SYM(vtl, g_vT_l)
    SYM(sc, g_s)     SYM(p16, g_p16)
    SYM(c16, g_ctx16)
    SYM(x1, g_x1)    SYM(y1, g_y1)  SYM(y116, g_y116)
    SYM(hh, g_h16a)
    SYM(x2, g_x2)
    #undef SYM

    cudaFuncSetAttribute(gemm_nt<1,0,0,0,0>, cudaFuncAttributeMaxDynamicSharedMemorySize, SMEM_TOTAL);
    cudaFuncSetAttribute(gemm_nt<0,1,0,0,0>, cudaFuncAttributeMaxDynamicSharedMemorySize, SMEM_TOTAL);
    cudaFuncSetAttribute(gemm_nt<0,0,1,0,0>, cudaFuncAttributeMaxDynamicSharedMemorySize, SMEM_TOTAL);
    cudaFuncSetAttribute(gemm_nt<0,1,0,1,0>, cudaFuncAttributeMaxDynamicSharedMemorySize, SMEM_TOTAL);
    cudaFuncSetAttribute(gemm_nt<1,0,0,0,1>, cudaFuncAttributeMaxDynamicSharedMemorySize, SMEM_TOTAL);

    dim3 blk(256);

    // 0. quantize x -> fp16
    quant_kernel<<<M_TOT * D_MODEL / 4 / 256, blk>>>(x, (h16*)x16_, M_TOT * D_MODEL / 4);

    // 1. transpose-split the four DxD weights
    transpose_split4_kernel<<<dim3(D_MODEL/32, D_MODEL/32, 4), blk>>>(
        wq, wk, wv, wo,
        (h16*)wqh_, (h16*)wql_, (h16*)wkh_, (h16*)wkl_,
        (h16*)wvh_, (h16*)wvl_, (h16*)woh_, (h16*)wol_);

    // 2-4. q (fp16 out), k (split out), v (fp32 out)   [launch #2 = GEMM]
    {
        dim3 g(D_MODEL/BN, M_TOT/BM, 1);
        gemm_nt<0,1,0,0,0><<<g, blk, SMEM_TOTAL>>>(
            (h16*)x16_, (h16*)wqh_, (h16*)wql_, bq, nullptr,
            nullptr, (h16*)q16_, nullptr, nullptr,
            M_TOT, D_MODEL, D_MODEL, 0, 0, 0);
        gemm_nt<0,0,1,0,0><<<g, blk, SMEM_TOTAL>>>(
            (h16*)x16_, (h16*)wkh_, (h16*)wkl_, bk, nullptr,
            nullptr, nullptr, (h16*)kh_, (h16*)kl_,
            M_TOT, D_MODEL, D_MODEL, 0, 0, 0);
        gemm_nt<1,0,0,0,0><<<g, blk, SMEM_TOTAL>>>(
            (h16*)x16_, (h16*)wvh_, (h16*)wvl_, bv, nullptr,
            (float*)vv_, nullptr, nullptr, nullptr,
            M_TOT, D_MODEL, D_MODEL, 0, 0, 0);
    }

    // 5-6. w1, w2 transposes
    transpose_split_kernel<<<dim3(FF_DIM/32, D_MODEL/32, 1), blk>>>(w1, (h16*)w1h_, (h16*)w1l_, D_MODEL, FF_DIM, 0, 0);
    transpose_split_kernel<<<dim3(D_MODEL/32, FF_DIM/32, 1), blk>>>(w2, (h16*)w2h_, (h16*)w2l_, FF_DIM, D_MODEL, 0, 0);

    // 7. vT per batch: [2048,1024] -> [1024,2048] hi/lo
    transpose_split_kernel<<<dim3(D_MODEL/32, SEQ/32, BATCH), blk>>>((float*)vv_,
        (h16*)vth_, (h16*)vtl_, SEQ, D_MODEL, (long long)SEQ*D_MODEL, (long long)SEQ*D_MODEL);

    // 8. scores = q @ k^T (fp32 out)
    gemm_nt<1,0,0,0,0><<<dim3(SEQ/BN, SEQ/BM, BATCH), blk, SMEM_TOTAL>>>(
        (h16*)q16_, (h16*)kh_, (h16*)kl_, nullptr, nullptr,
        (float*)sc_, nullptr, nullptr, nullptr,
        SEQ, SEQ, D_MODEL,
        (long long)SEQ*D_MODEL, (long long)SEQ*D_MODEL, (long long)SEQ*SEQ);

    // 9. softmax -> fp16 P
    softmax_kernel<<<BATCH*SEQ, blk>>>((float*)sc_, (h16*)p16_);

    // 10. ctx = P @ vT^T (fp16 out)
    gemm_nt<0,1,0,0,0><<<dim3(D_MODEL/BN, SEQ/BM, BATCH), blk, SMEM_TOTAL>>>(
        (h16*)p16_, (h16*)vth_, (h16*)vtl_, nullptr, nullptr,
        nullptr, (h16*)c16_, nullptr, nullptr,
        SEQ, D_MODEL, SEQ,
        (long long)SEQ*SEQ, (long long)SEQ*D_MODEL, (long long)SEQ*D_MODEL);

    // 11. x1 = x + ctx @ wo^T + bo
    gemm_nt<1,0,0,0,1><<<dim3(D_MODEL/BN, M_TOT/BM, 1), blk, SMEM_TOTAL>>>(
        (h16*)c16_, (h16*)woh_, (h16*)wol_, bo, x,
        (float*)x1_, nullptr, nullptr, nullptr,
        M_TOT, D_MODEL, D_MODEL, 0, 0, 0);

    // 12. y1 = LN1(x1), emit fp16
    layernorm_kernel<true><<<M_TOT, blk>>>((float*)x1_, g1, beta1, (float*)y1_, (h16*)y116_);

    // 13. h = relu(y1 @ w1^T + b1) (fp16 out)
    gemm_nt<0,1,0,1,0><<<dim3(FF_DIM/BN, M_TOT/BM, 1), blk, SMEM_TOTAL>>>(
        (h16*)y116_, (h16*)w1h_, (h16*)w1l_, b1, nullptr,
        nullptr, (h16*)hh_, nullptr, nullptr,
        M_TOT, FF_DIM, D_MODEL, 0, 0, 0);

    // 14. x2 = y1 + h @ w2^T + b2
    gemm_nt<1,0,0,0,1><<<dim3(D_MODEL/BN, M_TOT/BM, 1), blk, SMEM_TOTAL>>>(
        (h16*)hh_, (h16*)w2h_, (h16*)w2l_, b2, (float*)y1_,
        (float*)x2_, nullptr, nullptr, nullptr,
        M_TOT, D_MODEL, FF_DIM, 0, 0, 0);

    // 15. out = LN2(x2)
    layernorm_kernel<false><<<M_TOT, blk>>>((float*)x2_, g2, beta2, out, nullptr);
}

// round 11
// speedup vs baseline: 1.6354x; 1.6354x over previous
#include <cuda_runtime.h>
#include <cuda_fp16.h>
#include <math.h>
#include <stdint.h>

// ---------------------------------------------------------------------------
// SmallTransformerBlock via mma.sync single-pass fp16 GEMMs (sm_103 PTX).
// C = A16 @ B16^T, fp32 accumulate. Both operands fp16 (quantization error
// ~2^-12 each; measured chain error with A-only was 2.77e-4 -> predicted
// ~4e-4 total, gate is 1e-3).
// R11: based on R9 (best), lo-pass dropped everywhere. BK=64, SW128 swizzle,
// 2-stage cp.async, hoisted addressing, 2 CTAs/SM.
// ---------------------------------------------------------------------------

#define D_MODEL 1024
#define FF_DIM  4096
#define BATCH   4
#define SEQ     2048
#define M_TOT   (BATCH * SEQ)          // 8192

#define BM 128
#define BN 64
#define BK 64
#define STAGES 2
#define ABUF_BYTES (128 * 128)                 // A: 128 rows x 128B (64 fp16)
#define BBUF_BYTES (64 * 128)                  // B: 64 rows x 128B
#define STAGE_BYTES (ABUF_BYTES + BBUF_BYTES)  // 24576
#define SMEM_TOTAL  (STAGES * STAGE_BYTES)     // 49152

typedef __half h16;

// -------------------------- scratch (device globals) -----------------------
__device__ h16   g_x16  [M_TOT * D_MODEL];
__device__ h16   g_wqT  [D_MODEL * D_MODEL];
__device__ h16   g_wkT  [D_MODEL * D_MODEL];
__device__ h16   g_wvT  [D_MODEL * D_MODEL];
__device__ h16   g_woT  [D_MODEL * D_MODEL];
__device__ h16   g_w1T  [FF_DIM * D_MODEL];
__device__ h16   g_w2T  [D_MODEL * FF_DIM];
__device__ h16   g_q16  [M_TOT * D_MODEL];
__device__ h16   g_k16  [M_TOT * D_MODEL];
__device__ float g_v    [M_TOT * D_MODEL];
__device__ h16   g_vT16 [M_TOT * D_MODEL];     // [B][D,T]
__device__ float g_s    [BATCH * SEQ * SEQ];
__device__ h16   g_p16  [BATCH * SEQ * SEQ];
__device__ h16   g_ctx16[M_TOT * D_MODEL];
__device__ float g_x1   [M_TOT * D_MODEL];
__device__ float g_y1   [M_TOT * D_MODEL];
__device__ h16   g_y116 [M_TOT * D_MODEL];
__device__ h16   g_h16a [M_TOT * FF_DIM];
__device__ float g_x2   [M_TOT * D_MODEL];

// ------------------------------- PTX helpers -------------------------------
__device__ __forceinline__ uint32_t smem_u32(const void* p) {
    uint32_t a;
    asm("{ .reg .u64 t; cvta.to.shared.u64 t, %1; cvt.u32.u64 %0, t; }"
        : "=r"(a) : "l"(p));
    return a;
}
__device__ __forceinline__ void cp16(uint32_t dst, const void* src) {
    asm volatile("cp.async.cg.shared.global [%0], [%1], 16;\n" :: "r"(dst), "l"(src));
}
__device__ __forceinline__ void cp_commit() {
    asm volatile("cp.async.commit_group;\n" ::: "memory");
}
template<int N> __device__ __forceinline__ void cp_wait() {
    asm volatile("cp.async.wait_group %0;\n" :: "n"(N) : "memory");
}
__device__ __forceinline__ void ldsm4(uint32_t& r0, uint32_t& r1, uint32_t& r2,
                                      uint32_t& r3, uint32_t addr) {
    asm volatile("ldmatrix.sync.aligned.m8n8.x4.shared.b16 {%0,%1,%2,%3}, [%4];\n"
                 : "=r"(r0), "=r"(r1), "=r"(r2), "=r"(r3) : "r"(addr));
}
__device__ __forceinline__ void mma16816(float* d, const uint32_t* a, const uint32_t* b) {
    asm volatile(
        "mma.sync.aligned.m16n8k16.row.col.f32.f16.f16.f32 "
        "{%0,%1,%2,%3}, {%4,%5,%6,%7}, {%8,%9}, {%0,%1,%2,%3};\n"
        : "+f"(d[0]), "+f"(d[1]), "+f"(d[2]), "+f"(d[3])
        : "r"(a[0]), "r"(a[1]), "r"(a[2]), "r"(a[3]), "r"(b[0]), "r"(b[1]));
}
__device__ __forceinline__ uint32_t pack2h(h16 a, h16 b) {
    return ((uint32_t)__half_as_ushort(b) << 16) | __half_as_ushort(a);
}

// ---------------------------------------------------------------------------
// GEMM NT fp16 single-pass: C[M,N] = A16 @ B16^T (+bias)(relu)(+res)
// 128x64x64 tile, 8 warps (warp tile 32x32), 2-stage cp.async, 2 CTAs/SM.
// ---------------------------------------------------------------------------
template<bool F32OUT, bool HALFOUT, bool RELU, bool HASRES>
__global__ __launch_bounds__(256, 2) void gemm_nt(
    const h16* __restrict__ A16, const h16* __restrict__ B16,
    const float* __restrict__ bias, const float* __restrict__ Res,
    float* __restrict__ Cf, h16* __restrict__ Ch,
    int M, int N, int K, long long aS, long long bS, long long cS)
{
    extern __shared__ char smraw[];
    const uint32_t smb = smem_u32(smraw);
    const int tid  = threadIdx.x;
    const int wid  = tid >> 5;
    const int lane = tid & 31;
    const int wm = wid & 3;            // m offset wm*32
    const int wn = wid >> 2;           // n offset wn*32
    const int quad = lane >> 3, lrow = lane & 7;
    const int bz = blockIdx.z;
    const int bm = blockIdx.y * BM;
    const int bn = blockIdx.x * BN;

    // ---- hoisted global load pointers ----
    const int trow = tid >> 3;                 // 0..31
    const int lc   = tid & 7;                  // 16B chunk 0..7
    const int lk   = lc * 8;                   // k element offset
    const long long rowStep = 32LL * K;        // 32 rows, in elements
    const h16* pA = A16 + (long long)bz * aS + (long long)(bm + trow) * K + lk;
    const h16* pB = B16 + (long long)bz * bS + (long long)(bn + trow) * K + lk;
    const uint32_t d0 = (uint32_t)(trow * 128 + ((lc ^ (trow & 7)) * 16));

    // ---- hoisted ldsm base addresses (swizzle decomposed) ----
    const uint32_t bit4  = (uint32_t)(((quad >> 1) ^ (lrow & 1)) << 4);
    const uint32_t lrow6 = (uint32_t)(lrow & 6);
    uint32_t baseA[2], baseB[2];
    #pragma unroll
    for (int fm = 0; fm < 2; fm++)
        baseA[fm] = (uint32_t)((wm * 32 + fm * 16 + (quad & 1) * 8 + lrow) * 128) + bit4;
    #pragma unroll
    for (int f2 = 0; f2 < 2; f2++)
        baseB[f2] = ABUF_BYTES +
            (uint32_t)((wn * 32 + f2 * 16 + (quad & 1) * 8 + lrow) * 128) + bit4;

    float acc[2][4][4];
    #pragma unroll
    for (int i = 0; i < 2; i++)
        #pragma unroll
        for (int j = 0; j < 4; j++)
            #pragma unroll
            for (int c = 0; c < 4; c++) acc[i][j][c] = 0.0f;

    const int T = K / BK;

    auto load_stage = [&](int kt, int s) {
        const uint32_t stb = smb + (uint32_t)s * STAGE_BYTES;
        const int k0 = kt * BK;
        cp16(stb + d0,          pA + k0);
        cp16(stb + d0 + 4096,   pA + rowStep + k0);
        cp16(stb + d0 + 8192,   pA + 2 * rowStep + k0);
        cp16(stb + d0 + 12288,  pA + 3 * rowStep + k0);
        cp16(stb + ABUF_BYTES + d0,        pB + k0);
        cp16(stb + ABUF_BYTES + d0 + 4096, pB + rowStep + k0);
    };

    auto compute_stage = [&](int s) {
        const uint32_t stb = smb + (uint32_t)s * STAGE_BYTES;
        #pragma unroll
        for (int ks = 0; ks < 4; ks++) {
            const uint32_t kk = ((uint32_t)(ks * 2) ^ lrow6) << 4;
            uint32_t ah[2][4];
            #pragma unroll
            for (int fm = 0; fm < 2; fm++)
                ldsm4(ah[fm][0], ah[fm][1], ah[fm][2], ah[fm][3],
                      stb + baseA[fm] + kk);
            uint32_t bf[4][2];
            #pragma unroll
            for (int f2 = 0; f2 < 2; f2++) {
                uint32_t t0, t1, t2, t3;
                ldsm4(t0, t1, t2, t3, stb + baseB[f2] + kk);
                bf[2*f2][0] = t0; bf[2*f2][1] = t2;
                bf[2*f2+1][0] = t1; bf[2*f2+1][1] = t3;
            }
            #pragma unroll
            for (int fm = 0; fm < 2; fm++)
                #pragma unroll
                for (int fn = 0; fn < 4; fn++)
                    mma16816(acc[fm][fn], ah[fm], bf[fn]);
        }
    };

    load_stage(0, 0); cp_commit();
    load_stage(1, 1); cp_commit();

    for (int t = 0; t < T; t++) {
        if (t < T - 1) cp_wait<1>(); else cp_wait<0>();
        __syncthreads();
        compute_stage(t & 1);
        if (t < T - 2) {
            __syncthreads();
            load_stage(t + 2, t & 1); cp_commit();
        }
    }

    // ---------------- epilogue ----------------
    const int groupID = lane >> 2, tIdx = lane & 3;
    #pragma unroll
    for (int fm = 0; fm < 2; fm++) {
        #pragma unroll
        for (int half = 0; half < 2; half++) {
            int row = bm + wm * 32 + fm * 16 + half * 8 + groupID;
            long long rbase = (long long)bz * cS + (long long)row * N;
            #pragma unroll
            for (int fn = 0; fn < 4; fn++) {
                int col = bn + wn * 32 + fn * 8 + tIdx * 2;
                float v0 = acc[fm][fn][half * 2 + 0];
                float v1 = acc[fm][fn][half * 2 + 1];
                if (bias) { v0 += __ldg(bias + col); v1 += __ldg(bias + col + 1); }
                if (RELU) { v0 = fmaxf(v0, 0.0f); v1 = fmaxf(v1, 0.0f); }
                if (HASRES) {
                    float2 rv = *(const float2*)(Res + rbase + col);
                    v0 += rv.x; v1 += rv.y;
                }
                if (F32OUT)
                    *(float2*)(Cf + rbase + col) = make_float2(v0, v1);
                if (HALFOUT)
                    *(uint32_t*)(Ch + rbase + col) =
                        pack2h(__float2half_rn(v0), __float2half_rn(v1));
            }
        }
    }
}

// ---------------------------------------------------------------------------
// Elementwise quantize: fp32 -> fp16
// ---------------------------------------------------------------------------
__global__ __launch_bounds__(256) void quant_kernel(
    const float* __restrict__ src, h16* __restrict__ dst, int n4)
{
    int i = blockIdx.x * 256 + threadIdx.x;
    if (i >= n4) return;
    float4 v = ((const float4*)src)[i];
    ((uint2*)dst)[i] = make_uint2(
        pack2h(__float2half_rn(v.x), __float2half_rn(v.y)),
        pack2h(__float2half_rn(v.z), __float2half_rn(v.w)));
}

// ---------------------------------------------------------------------------
// Transpose-quantize: src [R,C] fp32 -> dst [C,R] fp16.
// ---------------------------------------------------------------------------
__global__ __launch_bounds__(256) void transpose_quant_kernel(
    const float* __restrict__ src, h16* __restrict__ dstT,
    int R, int C, long long sS, long long dS)
{
    __shared__ float tile[32][33];
    const float* S = src + (long long)blockIdx.z * sS;
    int c0 = blockIdx.x * 32, r0 = blockIdx.y * 32;
    int tx = threadIdx.x & 31, ty = threadIdx.x >> 5;   // 32 x 8
    #pragma unroll
    for (int i = 0; i < 32; i += 8)
        tile[ty + i][tx] = S[(long long)(r0 + ty + i) * C + c0 + tx];
    __syncthreads();
    #pragma unroll
    for (int i = 0; i < 32; i += 8) {
        long long o = (long long)blockIdx.z * dS + (long long)(c0 + ty + i) * R + r0 + tx;
        dstT[o] = __float2half_rn(tile[tx][ty + i]);
    }
}

// Batched: the four 1024x1024 weights in one launch (z picks the weight).
__global__ __launch_bounds__(256) void transpose_quant4_kernel(
    const float* __restrict__ s0, const float* __restrict__ s1,
    const float* __restrict__ s2, const float* __restrict__ s3,
    h16* __restrict__ d0p, h16* __restrict__ d1p,
    h16* __restrict__ d2p, h16* __restrict__ d3p)
{
    __shared__ float tile[32][33];
    const int z = blockIdx.z;
    const float* S = (z == 0) ? s0 : (z == 1) ? s1 : (z == 2) ? s2 : s3;
    h16* D = (z == 0) ? d0p : (z == 1) ? d1p : (z == 2) ? d2p : d3p;
    int c0 = blockIdx.x * 32, r0 = blockIdx.y * 32;
    int tx = threadIdx.x & 31, ty = threadIdx.x >> 5;
    #pragma unroll
    for (int i = 0; i < 32; i += 8)
        tile[ty + i][tx] = S[(long long)(r0 + ty + i) * D_MODEL + c0 + tx];
    __syncthreads();
    #pragma unroll
    for (int i = 0; i < 32; i += 8) {
        long long o = (long long)(c0 + ty + i) * D_MODEL + r0 + tx;
        D[o] = __float2half_rn(tile[tx][ty + i]);
    }
}

// ------------------------------- reductions --------------------------------
__device__ __forceinline__ float block_sum(float v) {
    __shared__ float sh[8];
    int lane = threadIdx.x & 31, w = threadIdx.x >> 5;
    #pragma unroll
    for (int o = 16; o > 0; o >>= 1) v += __shfl_xor_sync(0xffffffffu, v, o);
    if (lane == 0) sh[w] = v;
    __syncthreads();
    if (w == 0) {
        float t = (lane < 8) ? sh[lane] : 0.0f;
        #pragma unroll
        for (int o = 4; o > 0; o >>= 1) t += __shfl_xor_sync(0xffffffffu, t, o);
        if (lane == 0) sh[0] = t;
    }
    __syncthreads();
    float r = sh[0];
    __syncthreads();
    return r;
}
__device__ __forceinline__ float block_max(float v) {
    __shared__ float sh[8];
    int lane = threadIdx.x & 31, w = threadIdx.x >> 5;
    #pragma unroll
    for (int o = 16; o > 0; o >>= 1) v = fmaxf(v, __shfl_xor_sync(0xffffffffu, v, o));
    if (lane == 0) sh[w] = v;
    __syncthreads();
    if (w == 0) {
        float t = (lane < 8) ? sh[lane] : -3.4e38f;
        #pragma unroll
        for (int o = 4; o > 0; o >>= 1) t = fmaxf(t, __shfl_xor_sync(0xffffffffu, t, o));
        if (lane == 0) sh[0] = t;
    }
    __syncthreads();
    float r = sh[0];
    __syncthreads();
    return r;
}

// ---------------------------------------------------------------------------
// Softmax over SEQ=2048 with fused 1/scale; fp16 output.
// ---------------------------------------------------------------------------
__global__ __launch_bounds__(256) void softmax_kernel(
    const float* __restrict__ S, h16* __restrict__ P)
{
    const float inv_scale = 0.0883883476483184f;  // 1/sqrt(128)
    const float* row = S + (long long)blockIdx.x * SEQ;
    int tid = threadIdx.x;

    float4 a = ((const float4*)row)[tid];
    float4 b = ((const float4*)row)[tid + 256];
    a.x*=inv_scale; a.y*=inv_scale; a.z*=inv_scale; a.w*=inv_scale;
    b.x*=inv_scale; b.y*=inv_scale; b.z*=inv_scale; b.w*=inv_scale;

    float m = fmaxf(fmaxf(fmaxf(a.x,a.y), fmaxf(a.z,a.w)),
                    fmaxf(fmaxf(b.x,b.y), fmaxf(b.z,b.w)));
    m = block_max(m);
    a.x=expf(a.x-m); a.y=expf(a.y-m); a.z=expf(a.z-m); a.w=expf(a.w-m);
    b.x=expf(b.x-m); b.y=expf(b.y-m); b.z=expf(b.z-m); b.w=expf(b.w-m);
    float s = a.x+a.y+a.z+a.w + b.x+b.y+b.z+b.w;
    s = block_sum(s);
    float inv = 1.0f / s;
    a.x*=inv; a.y*=inv; a.z*=inv; a.w*=inv;
    b.x*=inv; b.y*=inv; b.z*=inv; b.w*=inv;

    long long base = (long long)blockIdx.x * SEQ;
    ((uint2*)(P + base))[tid] = make_uint2(
        pack2h(__float2half_rn(a.x), __float2half_rn(a.y)),
        pack2h(__float2half_rn(a.z), __float2half_rn(a.w)));
    ((uint2*)(P + base))[tid + 256] = make_uint2(
        pack2h(__float2half_rn(b.x), __float2half_rn(b.y)),
        pack2h(__float2half_rn(b.z), __float2half_rn(b.w)));
}

// ---------------------------------------------------------------------------
// LayerNorm D=1024; optional fp16 quantized emission.
// ---------------------------------------------------------------------------
template<bool EMITH>
__global__ __launch_bounds__(256) void layernorm_kernel(
    const float* __restrict__ X, const float* __restrict__ g,
    const float* __restrict__ b, float* __restrict__ Y, h16* __restrict__ Yh)
{
    const float* x = X + (long long)blockIdx.x * D_MODEL;
    int tid = threadIdx.x;
    float4 v = ((const float4*)x)[tid];
    float s = v.x + v.y + v.z + v.w;
    s = block_sum(s);
    float mean = s * (1.0f / D_MODEL);
    float dx=v.x-mean, dy=v.y-mean, dz=v.z-mean, dw=v.w-mean;
    float ss = dx*dx + dy*dy + dz*dz + dw*dw;
    ss = block_sum(ss);
    float rstd = rsqrtf(ss * (1.0f / D_MODEL) + 1e-5f);
    float4 gg = ((const float4*)g)[tid];
    float4 bb = ((const float4*)b)[tid];
    float4 o;
    o.x = dx*rstd*gg.x + bb.x;
    o.y = dy*rstd*gg.y + bb.y;
    o.z = dz*rstd*gg.z + bb.z;
    o.w = dw*rstd*gg.w + bb.w;
    long long base = (long long)blockIdx.x * D_MODEL;
    ((float4*)(Y + base))[tid] = o;
    if (EMITH) {
        ((uint2*)(Yh + base))[tid] = make_uint2(
            pack2h(__float2half_rn(o.x), __float2half_rn(o.y)),
            pack2h(__float2half_rn(o.z), __float2half_rn(o.w)));
    }
}

// ---------------------------------------------------------------------------
// Launch
// ---------------------------------------------------------------------------
extern "C" void kernel_launch(void* const* d_in, const int* in_sizes, int n_in,
                              void* d_out, int out_size)
{
    const float* x     = (const float*)d_in[0];
    const float* wq    = (const float*)d_in[1];
    const float* bq    = (const float*)d_in[2];
    const float* wk    = (const float*)d_in[3];
    const float* bk    = (const float*)d_in[4];
    const float* wv    = (const float*)d_in[5];
    const float* bv    = (const float*)d_in[6];
    const float* wo    = (const float*)d_in[7];
    const float* bo    = (const float*)d_in[8];
    const float* w1    = (const float*)d_in[9];
    const float* b1    = (const float*)d_in[10];
    const float* w2    = (const float*)d_in[11];
    const float* b2    = (const float*)d_in[12];
    const float* g1    = (const float*)d_in[13];
    const float* beta1 = (const float*)d_in[14];
    const float* g2    = (const float*)d_in[15];
    const float* beta2 = (const float*)d_in[16];
    float* out = (float*)d_out;

    #define SYM(p, s) void* p##_; cudaGetSymbolAddress(&p##_, s);
    SYM(x16, g_x16)
    SYM(wqT, g_wqT) SYM(wkT, g_wkT) SYM(wvT, g_wvT) SYM(woT, g_woT)
    SYM(w1T, g_w1T) SYM(w2T, g_w2T)
    SYM(q16, g_q16) SYM(k16, g_k16)
    SYM(vv, g_v)    SYM(vT16, g_vT16)
    SYM(sc, g_s)    SYM(p16, g_p16)
    SYM(c16, g_ctx16)
    SYM(x1, g_x1)   SYM(y1, g_y1)  SYM(y116, g_y116)
    SYM(hh, g_h16a)
    SYM(x2, g_x2)
    #undef SYM

    cudaFuncSetAttribute(gemm_nt<1,0,0,0>, cudaFuncAttributeMaxDynamicSharedMemorySize, SMEM_TOTAL);
    cudaFuncSetAttribute(gemm_nt<0,1,0,0>, cudaFuncAttributeMaxDynamicSharedMemorySize, SMEM_TOTAL);
    cudaFuncSetAttribute(gemm_nt<0,1,1,0>, cudaFuncAttributeMaxDynamicSharedMemorySize, SMEM_TOTAL);
    cudaFuncSetAttribute(gemm_nt<1,0,0,1>, cudaFuncAttributeMaxDynamicSharedMemorySize, SMEM_TOTAL);

    dim3 blk(256);

    // 0. quantize x -> fp16
    quant_kernel<<<M_TOT * D_MODEL / 4 / 256, blk>>>(x, (h16*)x16_, M_TOT * D_MODEL / 4);

    // 1. transpose-quantize the four DxD weights
    transpose_quant4_kernel<<<dim3(D_MODEL/32, D_MODEL/32, 4), blk>>>(
        wq, wk, wv, wo, (h16*)wqT_, (h16*)wkT_, (h16*)wvT_, (h16*)woT_);

    // 2-4. q, k (fp16 out), v (fp32 out)   [launch #2 = GEMM for ncu]
    {
        dim3 g(D_MODEL/BN, M_TOT/BM, 1);
        gemm_nt<0,1,0,0><<<g, blk, SMEM_TOTAL>>>(
            (h16*)x16_, (h16*)wqT_, bq, nullptr, nullptr, (h16*)q16_,
            M_TOT, D_MODEL, D_MODEL, 0, 0, 0);
        gemm_nt<0,1,0,0><<<g, blk, SMEM_TOTAL>>>(
            (h16*)x16_, (h16*)wkT_, bk, nullptr, nullptr, (h16*)k16_,
            M_TOT, D_MODEL, D_MODEL, 0, 0, 0);
        gemm_nt<1,0,0,0><<<g, blk, SMEM_TOTAL>>>(
            (h16*)x16_, (h16*)wvT_, bv, nullptr, (float*)vv_, nullptr,
            M_TOT, D_MODEL, D_MODEL, 0, 0, 0);
    }

    // 5-6. w1, w2 transposes
    transpose_quant_kernel<<<dim3(FF_DIM/32, D_MODEL/32, 1), blk>>>(
        w1, (h16*)w1T_, D_MODEL, FF_DIM, 0, 0);
    transpose_quant_kernel<<<dim3(D_MODEL/32, FF_DIM/32, 1), blk>>>(
        w2, (h16*)w2T_, FF_DIM, D_MODEL, 0, 0);

    // 7. vT per batch: [2048,1024] -> [1024,2048] fp16
    transpose_quant_kernel<<<dim3(D_MODEL/32, SEQ/32, BATCH), blk>>>(
        (float*)vv_, (h16*)vT16_, SEQ, D_MODEL,
        (long long)SEQ*D_MODEL, (long long)SEQ*D_MODEL);

    // 8. scores = q @ k^T (fp32 out)
    gemm_nt<1,0,0,0><<<dim3(SEQ/BN, SEQ/BM, BATCH), blk, SMEM_TOTAL>>>(
        (h16*)q16_, (h16*)k16_, nullptr, nullptr, (float*)sc_, nullptr,
        SEQ, SEQ, D_MODEL,
        (long long)SEQ*D_MODEL, (long long)SEQ*D_MODEL, (long long)SEQ*SEQ);

    // 9. softmax -> fp16 P
    softmax_kernel<<<BATCH*SEQ, blk>>>((float*)sc_, (h16*)p16_);

    // 10. ctx = P @ vT^T (fp16 out)
    gemm_nt<0,1,0,0><<<dim3(D_MODEL/BN, SEQ/BM, BATCH), blk, SMEM_TOTAL>>>(
        (h16*)p16_, (h16*)vT16_, nullptr, nullptr, nullptr, (h16*)c16_,
        SEQ, D_MODEL, SEQ,
        (long long)SEQ*SEQ, (long long)SEQ*D_MODEL, (long long)SEQ*D_MODEL);

    // 11. x1 = x + ctx @ wo^T + bo
    gemm_nt<1,0,0,1><<<dim3(D_MODEL/BN, M_TOT/BM, 1), blk, SMEM_TOTAL>>>(
        (h16*)c16_, (h16*)woT_, bo, x, (float*)x1_, nullptr,
        M_TOT, D_MODEL, D_MODEL, 0, 0, 0);

    // 12. y1 = LN1(x1), emit fp16
    layernorm_kernel<true><<<M_TOT, blk>>>((float*)x1_, g1, beta1, (float*)y1_, (h16*)y116_);

    // 13. h = relu(y1 @ w1^T + b1) (fp16 out)
    gemm_nt<0,1,1,0><<<dim3(FF_DIM/BN, M_TOT/BM, 1), blk, SMEM_TOTAL>>>(
        (h16*)y116_, (h16*)w1T_, b1, nullptr, nullptr, (h16*)hh_,
        M_TOT, FF_DIM, D_MODEL, 0, 0, 0);

    // 14. x2 = y1 + h @ w2^T + b2
    gemm_nt<1,0,0,1><<<dim3(D_MODEL/BN, M_TOT/BM, 1), blk, SMEM_TOTAL>>>(
        (h16*)hh_, (h16*)w2T_, b2, (float*)y1_, (float*)x2_, nullptr,
        M_TOT, D_MODEL, FF_DIM, 0, 0, 0);

    // 15. out = LN2(x2)
    layernorm_kernel<false><<<M_TOT, blk>>>((float*)x2_, g2, beta2, out, nullptr);
}

// round 12
// speedup vs baseline: 1.6964x; 1.0373x over previous
#include <cuda_runtime.h>
#include <cuda_fp16.h>
#include <math.h>
#include <stdint.h>

// ---------------------------------------------------------------------------
// SmallTransformerBlock via mma.sync single-pass fp16 GEMMs (sm_103 PTX).
// R12: BN=128 (warp tile 32x64) -> SMEM bytes/MAC 0.125 -> 0.094, raising the
// smem-crossbar-limited tensor ceiling from ~50% to ~67%.
// BK=64, SW128 swizzle, 2-stage cp.async (64KB/CTA), 2 CTAs/SM.
// ---------------------------------------------------------------------------

#define D_MODEL 1024
#define FF_DIM  4096
#define BATCH   4
#define SEQ     2048
#define M_TOT   (BATCH * SEQ)          // 8192

#define BM 128
#define BN 128
#define BK 64
#define STAGES 2
#define ABUF_BYTES (128 * 128)                 // A: 128 rows x 128B (64 fp16)
#define BBUF_BYTES (128 * 128)                 // B: 128 rows x 128B
#define STAGE_BYTES (ABUF_BYTES + BBUF_BYTES)  // 32768
#define SMEM_TOTAL  (STAGES * STAGE_BYTES)     // 65536

typedef __half h16;

// -------------------------- scratch (device globals) -----------------------
__device__ h16   g_x16  [M_TOT * D_MODEL];
__device__ h16   g_wqT  [D_MODEL * D_MODEL];
__device__ h16   g_wkT  [D_MODEL * D_MODEL];
__device__ h16   g_wvT  [D_MODEL * D_MODEL];
__device__ h16   g_woT  [D_MODEL * D_MODEL];
__device__ h16   g_w1T  [FF_DIM * D_MODEL];
__device__ h16   g_w2T  [D_MODEL * FF_DIM];
__device__ h16   g_q16  [M_TOT * D_MODEL];
__device__ h16   g_k16  [M_TOT * D_MODEL];
__device__ float g_v    [M_TOT * D_MODEL];
__device__ h16   g_vT16 [M_TOT * D_MODEL];     // [B][D,T]
__device__ float g_s    [BATCH * SEQ * SEQ];
__device__ h16   g_p16  [BATCH * SEQ * SEQ];
__device__ h16   g_ctx16[M_TOT * D_MODEL];
__device__ float g_x1   [M_TOT * D_MODEL];
__device__ float g_y1   [M_TOT * D_MODEL];
__device__ h16   g_y116 [M_TOT * D_MODEL];
__device__ h16   g_h16a [M_TOT * FF_DIM];
__device__ float g_x2   [M_TOT * D_MODEL];

// ------------------------------- PTX helpers -------------------------------
__device__ __forceinline__ uint32_t smem_u32(const void* p) {
    uint32_t a;
    asm("{ .reg .u64 t; cvta.to.shared.u64 t, %1; cvt.u32.u64 %0, t; }"
        : "=r"(a) : "l"(p));
    return a;
}
__device__ __forceinline__ void cp16(uint32_t dst, const void* src) {
    asm volatile("cp.async.cg.shared.global [%0], [%1], 16;\n" :: "r"(dst), "l"(src));
}
__device__ __forceinline__ void cp_commit() {
    asm volatile("cp.async.commit_group;\n" ::: "memory");
}
template<int N> __device__ __forceinline__ void cp_wait() {
    asm volatile("cp.async.wait_group %0;\n" :: "n"(N) : "memory");
}
__device__ __forceinline__ void ldsm4(uint32_t& r0, uint32_t& r1, uint32_t& r2,
                                      uint32_t& r3, uint32_t addr) {
    asm volatile("ldmatrix.sync.aligned.m8n8.x4.shared.b16 {%0,%1,%2,%3}, [%4];\n"
                 : "=r"(r0), "=r"(r1), "=r"(r2), "=r"(r3) : "r"(addr));
}
__device__ __forceinline__ void mma16816(float* d, const uint32_t* a, const uint32_t* b) {
    asm volatile(
        "mma.sync.aligned.m16n8k16.row.col.f32.f16.f16.f32 "
        "{%0,%1,%2,%3}, {%4,%5,%6,%7}, {%8,%9}, {%0,%1,%2,%3};\n"
        : "+f"(d[0]), "+f"(d[1]), "+f"(d[2]), "+f"(d[3])
        : "r"(a[0]), "r"(a[1]), "r"(a[2]), "r"(a[3]), "r"(b[0]), "r"(b[1]));
}
__device__ __forceinline__ uint32_t pack2h(h16 a, h16 b) {
    return ((uint32_t)__half_as_ushort(b) << 16) | __half_as_ushort(a);
}

// ---------------------------------------------------------------------------
// GEMM NT fp16: C[M,N] = A16 @ B16^T (+bias)(relu)(+res)
// 128x128x64 tile, 8 warps (warp tile 32x64), 2-stage cp.async, 2 CTAs/SM.
// ---------------------------------------------------------------------------
template<bool F32OUT, bool HALFOUT, bool RELU, bool HASRES>
__global__ __launch_bounds__(256, 2) void gemm_nt(
    const h16* __restrict__ A16, const h16* __restrict__ B16,
    const float* __restrict__ bias, const float* __restrict__ Res,
    float* __restrict__ Cf, h16* __restrict__ Ch,
    int M, int N, int K, long long aS, long long bS, long long cS)
{
    extern __shared__ char smraw[];
    const uint32_t smb = smem_u32(smraw);
    const int tid  = threadIdx.x;
    const int wid  = tid >> 5;
    const int lane = tid & 31;
    const int wm = wid & 3;            // m offset wm*32
    const int wn = wid >> 2;           // n offset wn*64
    const int quad = lane >> 3, lrow = lane & 7;
    const int bz = blockIdx.z;
    const int bm = blockIdx.y * BM;
    const int bn = blockIdx.x * BN;

    // ---- hoisted global load pointers ----
    const int trow = tid >> 3;                 // 0..31
    const int lc   = tid & 7;                  // 16B chunk 0..7
    const int lk   = lc * 8;                   // k element offset
    const long long rowStep = 32LL * K;        // 32 rows, in elements
    const h16* pA = A16 + (long long)bz * aS + (long long)(bm + trow) * K + lk;
    const h16* pB = B16 + (long long)bz * bS + (long long)(bn + trow) * K + lk;
    const uint32_t d0 = (uint32_t)(trow * 128 + ((lc ^ (trow & 7)) * 16));

    // ---- hoisted ldsm base addresses (swizzle decomposed) ----
    const uint32_t bit4  = (uint32_t)(((quad >> 1) ^ (lrow & 1)) << 4);
    const uint32_t lrow6 = (uint32_t)(lrow & 6);
    uint32_t baseA[2], baseB[4];
    #pragma unroll
    for (int fm = 0; fm < 2; fm++)
        baseA[fm] = (uint32_t)((wm * 32 + fm * 16 + (quad & 1) * 8 + lrow) * 128) + bit4;
    #pragma unroll
    for (int f2 = 0; f2 < 4; f2++)
        baseB[f2] = ABUF_BYTES +
            (uint32_t)((wn * 64 + f2 * 16 + (quad & 1) * 8 + lrow) * 128) + bit4;

    float acc[2][8][4];
    #pragma unroll
    for (int i = 0; i < 2; i++)
        #pragma unroll
        for (int j = 0; j < 8; j++)
            #pragma unroll
            for (int c = 0; c < 4; c++) acc[i][j][c] = 0.0f;

    const int T = K / BK;

    auto load_stage = [&](int kt, int s) {
        const uint32_t stb = smb + (uint32_t)s * STAGE_BYTES;
        const int k0 = kt * BK;
        cp16(stb + d0,          pA + k0);
        cp16(stb + d0 + 4096,   pA + rowStep + k0);
        cp16(stb + d0 + 8192,   pA + 2 * rowStep + k0);
        cp16(stb + d0 + 12288,  pA + 3 * rowStep + k0);
        cp16(stb + ABUF_BYTES + d0,          pB + k0);
        cp16(stb + ABUF_BYTES + d0 + 4096,   pB + rowStep + k0);
        cp16(stb + ABUF_BYTES + d0 + 8192,   pB + 2 * rowStep + k0);
        cp16(stb + ABUF_BYTES + d0 + 12288,  pB + 3 * rowStep + k0);
    };

    auto compute_stage = [&](int s) {
        const uint32_t stb = smb + (uint32_t)s * STAGE_BYTES;
        #pragma unroll
        for (int ks = 0; ks < 4; ks++) {
            const uint32_t kk = ((uint32_t)(ks * 2) ^ lrow6) << 4;
            uint32_t ah[2][4];
            #pragma unroll
            for (int fm = 0; fm < 2; fm++)
                ldsm4(ah[fm][0], ah[fm][1], ah[fm][2], ah[fm][3],
                      stb + baseA[fm] + kk);
            uint32_t bf[8][2];
            #pragma unroll
            for (int f2 = 0; f2 < 4; f2++) {
                uint32_t t0, t1, t2, t3;
                ldsm4(t0, t1, t2, t3, stb + baseB[f2] + kk);
                bf[2*f2][0] = t0; bf[2*f2][1] = t2;
                bf[2*f2+1][0] = t1; bf[2*f2+1][1] = t3;
            }
            #pragma unroll
            for (int fm = 0; fm < 2; fm++)
                #pragma unroll
                for (int fn = 0; fn < 8; fn++)
                    mma16816(acc[fm][fn], ah[fm], bf[fn]);
        }
    };

    load_stage(0, 0); cp_commit();
    load_stage(1, 1); cp_commit();

    for (int t = 0; t < T; t++) {
        if (t < T - 1) cp_wait<1>(); else cp_wait<0>();
        __syncthreads();
        compute_stage(t & 1);
        if (t < T - 2) {
            __syncthreads();
            load_stage(t + 2, t & 1); cp_commit();
        }
    }

    // ---------------- epilogue ----------------
    const int groupID = lane >> 2, tIdx = lane & 3;
    #pragma unroll
    for (int fm = 0; fm < 2; fm++) {
        #pragma unroll
        for (int half = 0; half < 2; half++) {
            int row = bm + wm * 32 + fm * 16 + half * 8 + groupID;
            long long rbase = (long long)bz * cS + (long long)row * N;
            #pragma unroll
            for (int fn = 0; fn < 8; fn++) {
                int col = bn + wn * 64 + fn * 8 + tIdx * 2;
                float v0 = acc[fm][fn][half * 2 + 0];
                float v1 = acc[fm][fn][half * 2 + 1];
                if (bias) { v0 += __ldg(bias + col); v1 += __ldg(bias + col + 1); }
                if (RELU) { v0 = fmaxf(v0, 0.0f); v1 = fmaxf(v1, 0.0f); }
                if (HASRES) {
                    float2 rv = *(const float2*)(Res + rbase + col);
                    v0 += rv.x; v1 += rv.y;
                }
                if (F32OUT)
                    *(float2*)(Cf + rbase + col) = make_float2(v0, v1);
                if (HALFOUT)
                    *(uint32_t*)(Ch + rbase + col) =
                        pack2h(__float2half_rn(v0), __float2half_rn(v1));
            }
        }
    }
}

// ---------------------------------------------------------------------------
// Elementwise quantize: fp32 -> fp16
// ---------------------------------------------------------------------------
__global__ __launch_bounds__(256) void quant_kernel(
    const float* __restrict__ src, h16* __restrict__ dst, int n4)
{
    int i = blockIdx.x * 256 + threadIdx.x;
    if (i >= n4) return;
    float4 v = ((const float4*)src)[i];
    ((uint2*)dst)[i] = make_uint2(
        pack2h(__float2half_rn(v.x), __float2half_rn(v.y)),
        pack2h(__float2half_rn(v.z), __float2half_rn(v.w)));
}

// ---------------------------------------------------------------------------
// Transpose-quantize: src [R,C] fp32 -> dst [C,R] fp16.
// ---------------------------------------------------------------------------
__global__ __launch_bounds__(256) void transpose_quant_kernel(
    const float* __restrict__ src, h16* __restrict__ dstT,
    int R, int C, long long sS, long long dS)
{
    __shared__ float tile[32][33];
    const float* S = src + (long long)blockIdx.z * sS;
    int c0 = blockIdx.x * 32, r0 = blockIdx.y * 32;
    int tx = threadIdx.x & 31, ty = threadIdx.x >> 5;   // 32 x 8
    #pragma unroll
    for (int i = 0; i < 32; i += 8)
        tile[ty + i][tx] = S[(long long)(r0 + ty + i) * C + c0 + tx];
    __syncthreads();
    #pragma unroll
    for (int i = 0; i < 32; i += 8) {
        long long o = (long long)blockIdx.z * dS + (long long)(c0 + ty + i) * R + r0 + tx;
        dstT[o] = __float2half_rn(tile[tx][ty + i]);
    }
}

// Batched: the four 1024x1024 weights in one launch (z picks the weight).
__global__ __launch_bounds__(256) void transpose_quant4_kernel(
    const float* __restrict__ s0, const float* __restrict__ s1,
    const float* __restrict__ s2, const float* __restrict__ s3,
    h16* __restrict__ d0p, h16* __restrict__ d1p,
    h16* __restrict__ d2p, h16* __restrict__ d3p)
{
    __shared__ float tile[32][33];
    const int z = blockIdx.z;
    const float* S = (z == 0) ? s0 : (z == 1) ? s1 : (z == 2) ? s2 : s3;
    h16* D = (z == 0) ? d0p : (z == 1) ? d1p : (z == 2) ? d2p : d3p;
    int c0 = blockIdx.x * 32, r0 = blockIdx.y * 32;
    int tx = threadIdx.x & 31, ty = threadIdx.x >> 5;
    #pragma unroll
    for (int i = 0; i < 32; i += 8)
        tile[ty + i][tx] = S[(long long)(r0 + ty + i) * D_MODEL + c0 + tx];
    __syncthreads();
    #pragma unroll
    for (int i = 0; i < 32; i += 8) {
        long long o = (long long)(c0 + ty + i) * D_MODEL + r0 + tx;
        D[o] = __float2half_rn(tile[tx][ty + i]);
    }
}

// ------------------------------- reductions --------------------------------
__device__ __forceinline__ float block_sum(float v) {
    __shared__ float sh[8];
    int lane = threadIdx.x & 31, w = threadIdx.x >> 5;
    #pragma unroll
    for (int o = 16; o > 0; o >>= 1) v += __shfl_xor_sync(0xffffffffu, v, o);
    if (lane == 0) sh[w] = v;
    __syncthreads();
    if (w == 0) {
        float t = (lane < 8) ? sh[lane] : 0.0f;
        #pragma unroll
        for (int o = 4; o > 0; o >>= 1) t += __shfl_xor_sync(0xffffffffu, t, o);
        if (lane == 0) sh[0] = t;
    }
    __syncthreads();
    float r = sh[0];
    __syncthreads();
    return r;
}
__device__ __forceinline__ float block_max(float v) {
    __shared__ float sh[8];
    int lane = threadIdx.x & 31, w = threadIdx.x >> 5;
    #pragma unroll
    for (int o = 16; o > 0; o >>= 1) v = fmaxf(v, __shfl_xor_sync(0xffffffffu, v, o));
    if (lane == 0) sh[w] = v;
    __syncthreads();
    if (w == 0) {
        float t = (lane < 8) ? sh[lane] : -3.4e38f;
        #pragma unroll
        for (int o = 4; o > 0; o >>= 1) t = fmaxf(t, __shfl_xor_sync(0xffffffffu, t, o));
        if (lane == 0) sh[0] = t;
    }
    __syncthreads();
    float r = sh[0];
    __syncthreads();
    return r;
}

// ---------------------------------------------------------------------------
// Softmax over SEQ=2048 with fused 1/scale; fp16 output.
// ---------------------------------------------------------------------------
__global__ __launch_bounds__(256) void softmax_kernel(
    const float* __restrict__ S, h16* __restrict__ P)
{
    const float inv_scale = 0.0883883476483184f;  // 1/sqrt(128)
    const float* row = S + (long long)blockIdx.x * SEQ;
    int tid = threadIdx.x;

    float4 a = ((const float4*)row)[tid];
    float4 b = ((const float4*)row)[tid + 256];
    a.x*=inv_scale; a.y*=inv_scale; a.z*=inv_scale; a.w*=inv_scale;
    b.x*=inv_scale; b.y*=inv_scale; b.z*=inv_scale; b.w*=inv_scale;

    float m = fmaxf(fmaxf(fmaxf(a.x,a.y), fmaxf(a.z,a.w)),
                    fmaxf(fmaxf(b.x,b.y), fmaxf(b.z,b.w)));
    m = block_max(m);
    a.x=expf(a.x-m); a.y=expf(a.y-m); a.z=expf(a.z-m); a.w=expf(a.w-m);
    b.x=expf(b.x-m); b.y=expf(b.y-m); b.z=expf(b.z-m); b.w=expf(b.w-m);
    float s = a.x+a.y+a.z+a.w + b.x+b.y+b.z+b.w;
    s = block_sum(s);
    float inv = 1.0f / s;
    a.x*=inv; a.y*=inv; a.z*=inv; a.w*=inv;
    b.x*=inv; b.y*=inv; b.z*=inv; b.w*=inv;

    long long base = (long long)blockIdx.x * SEQ;
    ((uint2*)(P + base))[tid] = make_uint2(
        pack2h(__float2half_rn(a.x), __float2half_rn(a.y)),
        pack2h(__float2half_rn(a.z), __float2half_rn(a.w)));
    ((uint2*)(P + base))[tid + 256] = make_uint2(
        pack2h(__float2half_rn(b.x), __float2half_rn(b.y)),
        pack2h(__float2half_rn(b.z), __float2half_rn(b.w)));
}

// ---------------------------------------------------------------------------
// LayerNorm D=1024; optional fp16 quantized emission.
// ---------------------------------------------------------------------------
template<bool EMITH>
__global__ __launch_bounds__(256) void layernorm_kernel(
    const float* __restrict__ X, const float* __restrict__ g,
    const float* __restrict__ b, float* __restrict__ Y, h16* __restrict__ Yh)
{
    const float* x = X + (long long)blockIdx.x * D_MODEL;
    int tid = threadIdx.x;
    float4 v = ((const float4*)x)[tid];
    float s = v.x + v.y + v.z + v.w;
    s = block_sum(s);
    float mean = s * (1.0f / D_MODEL);
    float dx=v.x-mean, dy=v.y-mean, dz=v.z-mean, dw=v.w-mean;
    float ss = dx*dx + dy*dy + dz*dz + dw*dw;
    ss = block_sum(ss);
    float rstd = rsqrtf(ss * (1.0f / D_MODEL) + 1e-5f);
    float4 gg = ((const float4*)g)[tid];
    float4 bb = ((const float4*)b)[tid];
    float4 o;
    o.x = dx*rstd*gg.x + bb.x;
    o.y = dy*rstd*gg.y + bb.y;
    o.z = dz*rstd*gg.z + bb.z;
    o.w = dw*rstd*gg.w + bb.w;
    long long base = (long long)blockIdx.x * D_MODEL;
    ((float4*)(Y + base))[tid] = o;
    if (EMITH) {
        ((uint2*)(Yh + base))[tid] = make_uint2(
            pack2h(__float2half_rn(o.x), __float2half_rn(o.y)),
            pack2h(__float2half_rn(o.z), __float2half_rn(o.w)));
    }
}

// ---------------------------------------------------------------------------
// Launch
// ---------------------------------------------------------------------------
extern "C" void kernel_launch(void* const* d_in, const int* in_sizes, int n_in,
                              void* d_out, int out_size)
{
    const float* x     = (const float*)d_in[0];
    const float* wq    = (const float*)d_in[1];
    const float* bq    = (const float*)d_in[2];
    const float* wk    = (const float*)d_in[3];
    const float* bk    = (const float*)d_in[4];
    const float* wv    = (const float*)d_in[5];
    const float* bv    = (const float*)d_in[6];
    const float* wo    = (const float*)d_in[7];
    const float* bo    = (const float*)d_in[8];
    const float* w1    = (const float*)d_in[9];
    const float* b1    = (const float*)d_in[10];
    const float* w2    = (const float*)d_in[11];
    const float* b2    = (const float*)d_in[12];
    const float* g1    = (const float*)d_in[13];
    const float* beta1 = (const float*)d_in[14];
    const float* g2    = (const float*)d_in[15];
    const float* beta2 = (const float*)d_in[16];
    float* out = (float*)d_out;

    #define SYM(p, s) void* p##_; cudaGetSymbolAddress(&p##_, s);
    SYM(x16, g_x16)
    SYM(wqT, g_wqT) SYM(wkT, g_wkT) SYM(wvT, g_wvT) SYM(woT, g_woT)
    SYM(w1T, g_w1T) SYM(w2T, g_w2T)
    SYM(q16, g_q16) SYM(k16, g_k16)
    SYM(vv, g_v)    SYM(vT16, g_vT16)
    SYM(sc, g_s)    SYM(p16, g_p16)
    SYM(c16, g_ctx16)
    SYM(x1, g_x1)   SYM(y1, g_y1)  SYM(y116, g_y116)
    SYM(hh, g_h16a)
    SYM(x2, g_x2)
    #undef SYM

    cudaFuncSetAttribute(gemm_nt<1,0,0,0>, cudaFuncAttributeMaxDynamicSharedMemorySize, SMEM_TOTAL);
    cudaFuncSetAttribute(gemm_nt<0,1,0,0>, cudaFuncAttributeMaxDynamicSharedMemorySize, SMEM_TOTAL);
    cudaFuncSetAttribute(gemm_nt<0,1,1,0>, cudaFuncAttributeMaxDynamicSharedMemorySize, SMEM_TOTAL);
    cudaFuncSetAttribute(gemm_nt<1,0,0,1>, cudaFuncAttributeMaxDynamicSharedMemorySize, SMEM_TOTAL);

    dim3 blk(256);

    // 0. quantize x -> fp16
    quant_kernel<<<M_TOT * D_MODEL / 4 / 256, blk>>>(x, (h16*)x16_, M_TOT * D_MODEL / 4);

    // 1. transpose-quantize the four DxD weights
    transpose_quant4_kernel<<<dim3(D_MODEL/32, D_MODEL/32, 4), blk>>>(
        wq, wk, wv, wo, (h16*)wqT_, (h16*)wkT_, (h16*)wvT_, (h16*)woT_);

    // 2-4. q, k (fp16 out), v (fp32 out)   [launch #2 = GEMM for ncu]
    {
        dim3 g(D_MODEL/BN, M_TOT/BM, 1);
        gemm_nt<0,1,0,0><<<g, blk, SMEM_TOTAL>>>(
            (h16*)x16_, (h16*)wqT_, bq, nullptr, nullptr, (h16*)q16_,
            M_TOT, D_MODEL, D_MODEL, 0, 0, 0);
        gemm_nt<0,1,0,0><<<g, blk, SMEM_TOTAL>>>(
            (h16*)x16_, (h16*)wkT_, bk, nullptr, nullptr, (h16*)k16_,
            M_TOT, D_MODEL, D_MODEL, 0, 0, 0);
        gemm_nt<1,0,0,0><<<g, blk, SMEM_TOTAL>>>(
            (h16*)x16_, (h16*)wvT_, bv, nullptr, (float*)vv_, nullptr,
            M_TOT, D_MODEL, D_MODEL, 0, 0, 0);
    }

    // 5-6. w1, w2 transposes
    transpose_quant_kernel<<<dim3(FF_DIM/32, D_MODEL/32, 1), blk>>>(
        w1, (h16*)w1T_, D_MODEL, FF_DIM, 0, 0);
    transpose_quant_kernel<<<dim3(D_MODEL/32, FF_DIM/32, 1), blk>>>(
        w2, (h16*)w2T_, FF_DIM, D_MODEL, 0, 0);

    // 7. vT per batch: [2048,1024] -> [1024,2048] fp16
    transpose_quant_kernel<<<dim3(D_MODEL/32, SEQ/32, BATCH), blk>>>(
        (float*)vv_, (h16*)vT16_, SEQ, D_MODEL,
        (long long)SEQ*D_MODEL, (long long)SEQ*D_MODEL);

    // 8. scores = q @ k^T (fp32 out)
    gemm_nt<1,0,0,0><<<dim3(SEQ/BN, SEQ/BM, BATCH), blk, SMEM_TOTAL>>>(
        (h16*)q16_, (h16*)k16_, nullptr, nullptr, (float*)sc_, nullptr,
        SEQ, SEQ, D_MODEL,
        (long long)SEQ*D_MODEL, (long long)SEQ*D_MODEL, (long long)SEQ*SEQ);

    // 9. softmax -> fp16 P
    softmax_kernel<<<BATCH*SEQ, blk>>>((float*)sc_, (h16*)p16_);

    // 10. ctx = P @ vT^T (fp16 out)
    gemm_nt<0,1,0,0><<<dim3(D_MODEL/BN, SEQ/BM, BATCH), blk, SMEM_TOTAL>>>(
        (h16*)p16_, (h16*)vT16_, nullptr, nullptr, nullptr, (h16*)c16_,
        SEQ, D_MODEL, SEQ,
        (long long)SEQ*SEQ, (long long)SEQ*D_MODEL, (long long)SEQ*D_MODEL);

    // 11. x1 = x + ctx @ wo^T + bo
    gemm_nt<1,0,0,1><<<dim3(D_MODEL/BN, M_TOT/BM, 1), blk, SMEM_TOTAL>>>(
        (h16*)c16_, (h16*)woT_, bo, x, (float*)x1_, nullptr,
        M_TOT, D_MODEL, D_MODEL, 0, 0, 0);

    // 12. y1 = LN1(x1), emit fp16
    layernorm_kernel<true><<<M_TOT, blk>>>((float*)x1_, g1, beta1, (float*)y1_, (h16*)y116_);

    // 13. h = relu(y1 @ w1^T + b1) (fp16 out)
    gemm_nt<0,1,1,0><<<dim3(FF_DIM/BN, M_TOT/BM, 1), blk, SMEM_TOTAL>>>(
        (h16*)y116_, (h16*)w1T_, b1, nullptr, nullptr, (h16*)hh_,
        M_TOT, FF_DIM, D_MODEL, 0, 0, 0);

    // 14. x2 = y1 + h @ w2^T + b2
    gemm_nt<1,0,0,1><<<dim3(D_MODEL/BN, M_TOT/BM, 1), blk, SMEM_TOTAL>>>(
        (h16*)hh_, (h16*)w2T_, b2, (float*)y1_, (float*)x2_, nullptr,
        M_TOT, D_MODEL, FF_DIM, 0, 0, 0);

    // 15. out = LN2(x2)
    layernorm_kernel<false><<<M_TOT, blk>>>((float*)x2_, g2, beta2, out, nullptr);
}

// round 13
// speedup vs baseline: 1.7296x; 1.0195x over previous
#include <cuda_runtime.h>
#include <cuda_fp16.h>
#include <math.h>
#include <stdint.h>

// ---------------------------------------------------------------------------
// SmallTransformerBlock via mma.sync single-pass fp16 GEMMs (sm_103 PTX).
// R13: 3-stage pipeline with ONE barrier/stage and cp.async interleaved into
// the ks loop (load/compute overlap); QKV fused into one N=3072 GEMM with
// strided views; v emitted fp16 directly (no fp32 round-trip).
// ---------------------------------------------------------------------------

#define D_MODEL 1024
#define FF_DIM  4096
#define BATCH   4
#define SEQ     2048
#define M_TOT   (BATCH * SEQ)          // 8192
#define QKV_N   (3 * D_MODEL)          // 3072

#define BM 128
#define BN 128
#define BK 64
#define STAGES 3
#define ABUF_BYTES (128 * 128)
#define BBUF_BYTES (128 * 128)
#define STAGE_BYTES (ABUF_BYTES + BBUF_BYTES)  // 32768
#define SMEM_TOTAL  (STAGES * STAGE_BYTES)     // 98304

typedef __half h16;

// -------------------------- scratch (device globals) -----------------------
__device__ h16   g_x16   [M_TOT * D_MODEL];
__device__ h16   g_wqkvT [QKV_N * D_MODEL];    // rows 0-1023 wq^T, 1024-2047 wk^T, 2048-3071 wv^T
__device__ h16   g_woT   [D_MODEL * D_MODEL];
__device__ h16   g_w1T   [FF_DIM * D_MODEL];
__device__ h16   g_w2T   [D_MODEL * FF_DIM];
__device__ float g_bqkv  [QKV_N];
__device__ h16   g_qkv16 [M_TOT * QKV_N];      // [B*T, 3072]
__device__ h16   g_vT16  [M_TOT * D_MODEL];    // [B][D, T]
__device__ float g_s     [BATCH * SEQ * SEQ];
__device__ h16   g_p16   [BATCH * SEQ * SEQ];
__device__ h16   g_ctx16 [M_TOT * D_MODEL];
__device__ float g_x1    [M_TOT * D_MODEL];
__device__ float g_y1    [M_TOT * D_MODEL];
__device__ h16   g_y116  [M_TOT * D_MODEL];
__device__ h16   g_h16a  [M_TOT * FF_DIM];
__device__ float g_x2    [M_TOT * D_MODEL];

// ------------------------------- PTX helpers -------------------------------
__device__ __forceinline__ uint32_t smem_u32(const void* p) {
    uint32_t a;
    asm("{ .reg .u64 t; cvta.to.shared.u64 t, %1; cvt.u32.u64 %0, t; }"
        : "=r"(a) : "l"(p));
    return a;
}
__device__ __forceinline__ void cp16(uint32_t dst, const void* src) {
    asm volatile("cp.async.cg.shared.global [%0], [%1], 16;\n" :: "r"(dst), "l"(src));
}
__device__ __forceinline__ void cp_commit() {
    asm volatile("cp.async.commit_group;\n" ::: "memory");
}
template<int N> __device__ __forceinline__ void cp_wait() {
    asm volatile("cp.async.wait_group %0;\n" :: "n"(N) : "memory");
}
__device__ __forceinline__ void ldsm4(uint32_t& r0, uint32_t& r1, uint32_t& r2,
                                      uint32_t& r3, uint32_t addr) {
    asm volatile("ldmatrix.sync.aligned.m8n8.x4.shared.b16 {%0,%1,%2,%3}, [%4];\n"
                 : "=r"(r0), "=r"(r1), "=r"(r2), "=r"(r3) : "r"(addr));
}
__device__ __forceinline__ void mma16816(float* d, const uint32_t* a, const uint32_t* b) {
    asm volatile(
        "mma.sync.aligned.m16n8k16.row.col.f32.f16.f16.f32 "
        "{%0,%1,%2,%3}, {%4,%5,%6,%7}, {%8,%9}, {%0,%1,%2,%3};\n"
        : "+f"(d[0]), "+f"(d[1]), "+f"(d[2]), "+f"(d[3])
        : "r"(a[0]), "r"(a[1]), "r"(a[2]), "r"(a[3]), "r"(b[0]), "r"(b[1]));
}
__device__ __forceinline__ uint32_t pack2h(h16 a, h16 b) {
    return ((uint32_t)__half_as_ushort(b) << 16) | __half_as_ushort(a);
}

// ---------------------------------------------------------------------------
// GEMM NT fp16: C[M,N] = A16 @ B16^T (+bias)(relu)(+res), strided operands.
// 128x128x64 tile, 8 warps (warp tile 32x64), 3-stage pipeline, 1 barrier
// per stage, cp.async interleaved into the ks loop. 2 CTAs/SM.
// ---------------------------------------------------------------------------
template<bool F32OUT, bool HALFOUT, bool RELU, bool HASRES>
__global__ __launch_bounds__(256, 2) void gemm_nt(
    const h16* __restrict__ A16, const h16* __restrict__ B16,
    const float* __restrict__ bias, const float* __restrict__ Res,
    float* __restrict__ Cf, h16* __restrict__ Ch,
    int M, int N, int K, int lda, int ldb, int ldc,
    long long aS, long long bS, long long cS)
{
    extern __shared__ char smraw[];
    const uint32_t smb = smem_u32(smraw);
    const int tid  = threadIdx.x;
    const int wid  = tid >> 5;
    const int lane = tid & 31;
    const int wm = wid & 3;            // m offset wm*32
    const int wn = wid >> 2;           // n offset wn*64
    const int quad = lane >> 3, lrow = lane & 7;
    const int bz = blockIdx.z;
    const int bm = blockIdx.y * BM;
    const int bn = blockIdx.x * BN;

    // ---- hoisted global load pointers ----
    const int trow = tid >> 3;                 // 0..31
    const int lc   = tid & 7;                  // 16B chunk 0..7
    const int lk   = lc * 8;                   // k element offset
    const long long rowStepA = 32LL * lda;
    const long long rowStepB = 32LL * ldb;
    const h16* pA = A16 + (long long)bz * aS + (long long)(bm + trow) * lda + lk;
    const h16* pB = B16 + (long long)bz * bS + (long long)(bn + trow) * ldb + lk;
    const uint32_t d0 = (uint32_t)(trow * 128 + ((lc ^ (trow & 7)) * 16));

    // ---- hoisted ldsm base addresses ----
    const uint32_t bit4  = (uint32_t)(((quad >> 1) ^ (lrow & 1)) << 4);
    const uint32_t lrow6 = (uint32_t)(lrow & 6);
    uint32_t baseA[2], baseB[4];
    #pragma unroll
    for (int fm = 0; fm < 2; fm++)
        baseA[fm] = (uint32_t)((wm * 32 + fm * 16 + (quad & 1) * 8 + lrow) * 128) + bit4;
    #pragma unroll
    for (int f2 = 0; f2 < 4; f2++)
        baseB[f2] = ABUF_BYTES +
            (uint32_t)((wn * 64 + f2 * 16 + (quad & 1) * 8 + lrow) * 128) + bit4;

    float acc[2][8][4];
    #pragma unroll
    for (int i = 0; i < 2; i++)
        #pragma unroll
        for (int j = 0; j < 8; j++)
            #pragma unroll
            for (int c = 0; c < 4; c++) acc[i][j][c] = 0.0f;

    const int T = K / BK;

    // one 16B chunk of a stage load: idx 0-3 = A rows, 4-7 = B rows
    auto cp_one = [&](int idx, int k0, uint32_t stb) {
        if (idx < 4)
            cp16(stb + d0 + (uint32_t)idx * 4096, pA + (long long)idx * rowStepA + k0);
        else
            cp16(stb + ABUF_BYTES + d0 + (uint32_t)(idx - 4) * 4096,
                 pB + (long long)(idx - 4) * rowStepB + k0);
    };
    auto load_stage = [&](int kt, int s) {
        const uint32_t stb = smb + (uint32_t)s * STAGE_BYTES;
        const int k0 = kt * BK;
        #pragma unroll
        for (int i = 0; i < 8; i++) cp_one(i, k0, stb);
    };

    load_stage(0, 0); cp_commit();
    load_stage(1, 1); cp_commit();

    int sCur = 0, sLd = 2;
    for (int t = 0; t < T; t++) {
        cp_wait<1>();
        __syncthreads();
        const uint32_t stb  = smb + (uint32_t)sCur * STAGE_BYTES;
        const uint32_t stbL = smb + (uint32_t)sLd * STAGE_BYTES;
        const bool doLoad = (t + 2 < T);
        const int k0n = (t + 2) * BK;

        #pragma unroll
        for (int ks = 0; ks < 4; ks++) {
            const uint32_t kk = ((uint32_t)(ks * 2) ^ lrow6) << 4;
            uint32_t ah[2][4];
            #pragma unroll
            for (int fm = 0; fm < 2; fm++)
                ldsm4(ah[fm][0], ah[fm][1], ah[fm][2], ah[fm][3],
                      stb + baseA[fm] + kk);
            uint32_t bf[8][2];
            #pragma unroll
            for (int f2 = 0; f2 < 4; f2++) {
                uint32_t t0, t1, t2, t3;
                ldsm4(t0, t1, t2, t3, stb + baseB[f2] + kk);
                bf[2*f2][0] = t0; bf[2*f2][1] = t2;
                bf[2*f2+1][0] = t1; bf[2*f2+1][1] = t3;
            }
            if (doLoad) {               // trickle the next-next stage's load
                cp_one(ks * 2,     k0n, stbL);
                cp_one(ks * 2 + 1, k0n, stbL);
            }
            #pragma unroll
            for (int fm = 0; fm < 2; fm++)
                #pragma unroll
                for (int fn = 0; fn < 8; fn++)
                    mma16816(acc[fm][fn], ah[fm], bf[fn]);
        }
        cp_commit();
        sCur = (sCur == 2) ? 0 : sCur + 1;
        sLd  = (sLd  == 2) ? 0 : sLd  + 1;
    }

    // ---------------- epilogue ----------------
    const int groupID = lane >> 2, tIdx = lane & 3;
    #pragma unroll
    for (int fm = 0; fm < 2; fm++) {
        #pragma unroll
        for (int half = 0; half < 2; half++) {
            int row = bm + wm * 32 + fm * 16 + half * 8 + groupID;
            long long rbase = (long long)bz * cS + (long long)row * ldc;
            #pragma unroll
            for (int fn = 0; fn < 8; fn++) {
                int col = bn + wn * 64 + fn * 8 + tIdx * 2;
                float v0 = acc[fm][fn][half * 2 + 0];
                float v1 = acc[fm][fn][half * 2 + 1];
                if (bias) { v0 += __ldg(bias + col); v1 += __ldg(bias + col + 1); }
                if (RELU) { v0 = fmaxf(v0, 0.0f); v1 = fmaxf(v1, 0.0f); }
                if (HASRES) {
                    float2 rv = *(const float2*)(Res + rbase + col);
                    v0 += rv.x; v1 += rv.y;
                }
                if (F32OUT)
                    *(float2*)(Cf + rbase + col) = make_float2(v0, v1);
                if (HALFOUT)
                    *(uint32_t*)(Ch + rbase + col) =
                        pack2h(__float2half_rn(v0), __float2half_rn(v1));
            }
        }
    }
}

// ---------------------------------------------------------------------------
// Elementwise quantize: fp32 -> fp16
// ---------------------------------------------------------------------------
__global__ __launch_bounds__(256) void quant_kernel(
    const float* __restrict__ src, h16* __restrict__ dst, int n4)
{
    int i = blockIdx.x * 256 + threadIdx.x;
    if (i >= n4) return;
    float4 v = ((const float4*)src)[i];
    ((uint2*)dst)[i] = make_uint2(
        pack2h(__float2half_rn(v.x), __float2half_rn(v.y)),
        pack2h(__float2half_rn(v.z), __float2half_rn(v.w)));
}

// bias concat: [bq | bk | bv] -> g_bqkv
__global__ __launch_bounds__(256) void bias_concat_kernel(
    const float* __restrict__ bq, const float* __restrict__ bk,
    const float* __restrict__ bv, float* __restrict__ dst)
{
    int i = blockIdx.x * 256 + threadIdx.x;
    if (i >= QKV_N) return;
    float v = (i < D_MODEL) ? bq[i]
            : (i < 2 * D_MODEL) ? bk[i - D_MODEL] : bv[i - 2 * D_MODEL];
    dst[i] = v;
}

// ---------------------------------------------------------------------------
// Transpose-quantize: src [R,C] fp32 -> dst [C,R] fp16.
// ---------------------------------------------------------------------------
__global__ __launch_bounds__(256) void transpose_quant_kernel(
    const float* __restrict__ src, h16* __restrict__ dstT,
    int R, int C, long long sS, long long dS)
{
    __shared__ float tile[32][33];
    const float* S = src + (long long)blockIdx.z * sS;
    int c0 = blockIdx.x * 32, r0 = blockIdx.y * 32;
    int tx = threadIdx.x & 31, ty = threadIdx.x >> 5;   // 32 x 8
    #pragma unroll
    for (int i = 0; i < 32; i += 8)
        tile[ty + i][tx] = S[(long long)(r0 + ty + i) * C + c0 + tx];
    __syncthreads();
    #pragma unroll
    for (int i = 0; i < 32; i += 8) {
        long long o = (long long)blockIdx.z * dS + (long long)(c0 + ty + i) * R + r0 + tx;
        dstT[o] = __float2half_rn(tile[tx][ty + i]);
    }
}

// fp16 strided transpose: src [R rows, stride ldS] -> dst [C, R]
__global__ __launch_bounds__(256) void transpose16_kernel(
    const h16* __restrict__ src, h16* __restrict__ dstT,
    int R, int ldS, long long sS, long long dS)
{
    __shared__ h16 tile[32][33];
    const h16* S = src + (long long)blockIdx.z * sS;
    int c0 = blockIdx.x * 32, r0 = blockIdx.y * 32;
    int tx = threadIdx.x & 31, ty = threadIdx.x >> 5;
    #pragma unroll
    for (int i = 0; i < 32; i += 8)
        tile[ty + i][tx] = S[(long long)(r0 + ty + i) * ldS + c0 + tx];
    __syncthreads();
    #pragma unroll
    for (int i = 0; i < 32; i += 8) {
        long long o = (long long)blockIdx.z * dS + (long long)(c0 + ty + i) * R + r0 + tx;
        dstT[o] = tile[tx][ty + i];
    }
}

// Batched: the four 1024x1024 weights in one launch (z picks the weight).
__global__ __launch_bounds__(256) void transpose_quant4_kernel(
    const float* __restrict__ s0, const float* __restrict__ s1,
    const float* __restrict__ s2, const float* __restrict__ s3,
    h16* __restrict__ d0p, h16* __restrict__ d1p,
    h16* __restrict__ d2p, h16* __restrict__ d3p)
{
    __shared__ float tile[32][33];
    const int z = blockIdx.z;
    const float* S = (z == 0) ? s0 : (z == 1) ? s1 : (z == 2) ? s2 : s3;
    h16* D = (z == 0) ? d0p : (z == 1) ? d1p : (z == 2) ? d2p : d3p;
    int c0 = blockIdx.x * 32, r0 = blockIdx.y * 32;
    int tx = threadIdx.x & 31, ty = threadIdx.x >> 5;
    #pragma unroll
    for (int i = 0; i < 32; i += 8)
        tile[ty + i][tx] = S[(long long)(r0 + ty + i) * D_MODEL + c0 + tx];
    __syncthreads();
    #pragma unroll
    for (int i = 0; i < 32; i += 8) {
        long long o = (long long)(c0 + ty + i) * D_MODEL + r0 + tx;
        D[o] = __float2half_rn(tile[tx][ty + i]);
    }
}

// ------------------------------- reductions --------------------------------
__device__ __forceinline__ float block_sum(float v) {
    __shared__ float sh[8];
    int lane = threadIdx.x & 31, w = threadIdx.x >> 5;
    #pragma unroll
    for (int o = 16; o > 0; o >>= 1) v += __shfl_xor_sync(0xffffffffu, v, o);
    if (lane == 0) sh[w] = v;
    __syncthreads();
    if (w == 0) {
        float t = (lane < 8) ? sh[lane] : 0.0f;
        #pragma unroll
        for (int o = 4; o > 0; o >>= 1) t += __shfl_xor_sync(0xffffffffu, t, o);
        if (lane == 0) sh[0] = t;
    }
    __syncthreads();
    float r = sh[0];
    __syncthreads();
    return r;
}
__device__ __forceinline__ float block_max(float v) {
    __shared__ float sh[8];
    int lane = threadIdx.x & 31, w = threadIdx.x >> 5;
    #pragma unroll
    for (int o = 16; o > 0; o >>= 1) v = fmaxf(v, __shfl_xor_sync(0xffffffffu, v, o));
    if (lane == 0) sh[w] = v;
    __syncthreads();
    if (w == 0) {
        float t = (lane < 8) ? sh[lane] : -3.4e38f;
        #pragma unroll
        for (int o = 4; o > 0; o >>= 1) t = fmaxf(t, __shfl_xor_sync(0xffffffffu, t, o));
        if (lane == 0) sh[0] = t;
    }
    __syncthreads();
    float r = sh[0];
    __syncthreads();
    return r;
}

// ---------------------------------------------------------------------------
// Softmax over SEQ=2048 with fused 1/scale; fp16 output.
// ---------------------------------------------------------------------------
__global__ __launch_bounds__(256) void softmax_kernel(
    const float* __restrict__ S, h16* __restrict__ P)
{
    const float inv_scale = 0.0883883476483184f;  // 1/sqrt(128)
    const float* row = S + (long long)blockIdx.x * SEQ;
    int tid = threadIdx.x;

    float4 a = ((const float4*)row)[tid];
    float4 b = ((const float4*)row)[tid + 256];
    a.x*=inv_scale; a.y*=inv_scale; a.z*=inv_scale; a.w*=inv_scale;
    b.x*=inv_scale; b.y*=inv_scale; b.z*=inv_scale; b.w*=inv_scale;

    float m = fmaxf(fmaxf(fmaxf(a.x,a.y), fmaxf(a.z,a.w)),
                    fmaxf(fmaxf(b.x,b.y), fmaxf(b.z,b.w)));
    m = block_max(m);
    a.x=expf(a.x-m); a.y=expf(a.y-m); a.z=expf(a.z-m); a.w=expf(a.w-m);
    b.x=expf(b.x-m); b.y=expf(b.y-m); b.z=expf(b.z-m); b.w=expf(b.w-m);
    float s = a.x+a.y+a.z+a.w + b.x+b.y+b.z+b.w;
    s = block_sum(s);
    float inv = 1.0f / s;
    a.x*=inv; a.y*=inv; a.z*=inv; a.w*=inv;
    b.x*=inv; b.y*=inv; b.z*=inv; b.w*=inv;

    long long base = (long long)blockIdx.x * SEQ;
    ((uint2*)(P + base))[tid] = make_uint2(
        pack2h(__float2half_rn(a.x), __float2half_rn(a.y)),
        pack2h(__float2half_rn(a.z), __float2half_rn(a.w)));
    ((uint2*)(P + base))[tid + 256] = make_uint2(
        pack2h(__float2half_rn(b.x), __float2half_rn(b.y)),
        pack2h(__float2half_rn(b.z), __float2half_rn(b.w)));
}

// ---------------------------------------------------------------------------
// LayerNorm D=1024; optional fp16 quantized emission.
// ---------------------------------------------------------------------------
template<bool EMITH>
__global__ __launch_bounds__(256) void layernorm_kernel(
    const float* __restrict__ X, const float* __restrict__ g,
    const float* __restrict__ b, float* __restrict__ Y, h16* __restrict__ Yh)
{
    const float* x = X + (long long)blockIdx.x * D_MODEL;
    int tid = threadIdx.x;
    float4 v = ((const float4*)x)[tid];
    float s = v.x + v.y + v.z + v.w;
    s = block_sum(s);
    float mean = s * (1.0f / D_MODEL);
    float dx=v.x-mean, dy=v.y-mean, dz=v.z-mean, dw=v.w-mean;
    float ss = dx*dx + dy*dy + dz*dz + dw*dw;
    ss = block_sum(ss);
    float rstd = rsqrtf(ss * (1.0f / D_MODEL) + 1e-5f);
    float4 gg = ((const float4*)g)[tid];
    float4 bb = ((const float4*)b)[tid];
    float4 o;
    o.x = dx*rstd*gg.x + bb.x;
    o.y = dy*rstd*gg.y + bb.y;
    o.z = dz*rstd*gg.z + bb.z;
    o.w = dw*rstd*gg.w + bb.w;
    long long base = (long long)blockIdx.x * D_MODEL;
    ((float4*)(Y + base))[tid] = o;
    if (EMITH) {
        ((uint2*)(Yh + base))[tid] = make_uint2(
            pack2h(__float2half_rn(o.x), __float2half_rn(o.y)),
            pack2h(__float2half_rn(o.z), __float2half_rn(o.w)));
    }
}

// ---------------------------------------------------------------------------
// Launch
// ---------------------------------------------------------------------------
extern "C" void kernel_launch(void* const* d_in, const int* in_sizes, int n_in,
                              void* d_out, int out_size)
{
    const float* x     = (const float*)d_in[0];
    const float* wq    = (const float*)d_in[1];
    const float* bq    = (const float*)d_in[2];
    const float* wk    = (const float*)d_in[3];
    const float* bk    = (const float*)d_in[4];
    const float* wv    = (const float*)d_in[5];
    const float* bv    = (const float*)d_in[6];
    const float* wo    = (const float*)d_in[7];
    const float* bo    = (const float*)d_in[8];
    const float* w1    = (const float*)d_in[9];
    const float* b1    = (const float*)d_in[10];
    const float* w2    = (const float*)d_in[11];
    const float* b2    = (const float*)d_in[12];
    const float* g1    = (const float*)d_in[13];
    const float* beta1 = (const float*)d_in[14];
    const float* g2    = (const float*)d_in[15];
    const float* beta2 = (const float*)d_in[16];
    float* out = (float*)d_out;

    #define SYM(p, s) void* p##_; cudaGetSymbolAddress(&p##_, s);
    SYM(x16, g_x16)
    SYM(wqkvT, g_wqkvT) SYM(woT, g_woT)
    SYM(w1T, g_w1T) SYM(w2T, g_w2T)
    SYM(bqkv, g_bqkv)
    SYM(qkv16, g_qkv16)
    SYM(vT16, g_vT16)
    SYM(sc, g_s)    SYM(p16, g_p16)
    SYM(c16, g_ctx16)
    SYM(x1, g_x1)   SYM(y1, g_y1)  SYM(y116, g_y116)
    SYM(hh, g_h16a)
    SYM(x2, g_x2)
    #undef SYM

    cudaFuncSetAttribute(gemm_nt<1,0,0,0>, cudaFuncAttributeMaxDynamicSharedMemorySize, SMEM_TOTAL);
    cudaFuncSetAttribute(gemm_nt<0,1,0,0>, cudaFuncAttributeMaxDynamicSharedMemorySize, SMEM_TOTAL);
    cudaFuncSetAttribute(gemm_nt<0,1,1,0>, cudaFuncAttributeMaxDynamicSharedMemorySize, SMEM_TOTAL);
    cudaFuncSetAttribute(gemm_nt<1,0,0,1>, cudaFuncAttributeMaxDynamicSharedMemorySize, SMEM_TOTAL);

    dim3 blk(256);
    h16* qkv = (h16*)qkv16_;

    // 0. quantize x -> fp16
    quant_kernel<<<M_TOT * D_MODEL / 4 / 256, blk>>>(x, (h16*)x16_, M_TOT * D_MODEL / 4);

    // 1. transpose-quantize wq,wk,wv into wqkvT blocks; wo into woT
    transpose_quant4_kernel<<<dim3(D_MODEL/32, D_MODEL/32, 4), blk>>>(
        wq, wk, wv, wo,
        (h16*)wqkvT_, (h16*)wqkvT_ + D_MODEL*D_MODEL,
        (h16*)wqkvT_ + 2*D_MODEL*D_MODEL, (h16*)woT_);

    // 2. concat biases
    bias_concat_kernel<<<(QKV_N + 255)/256, blk>>>(bq, bk, bv, (float*)bqkv_);

    // 3. fused QKV GEMM: [8192,1024] @ [3072,1024]^T -> qkv16 [8192,3072]
    gemm_nt<0,1,0,0><<<dim3(QKV_N/BN, M_TOT/BM, 1), blk, SMEM_TOTAL>>>(
        (h16*)x16_, (h16*)wqkvT_, (float*)bqkv_, nullptr, nullptr, qkv,
        M_TOT, QKV_N, D_MODEL, D_MODEL, D_MODEL, QKV_N, 0, 0, 0);

    // 4-5. w1, w2 transposes
    transpose_quant_kernel<<<dim3(FF_DIM/32, D_MODEL/32, 1), blk>>>(
        w1, (h16*)w1T_, D_MODEL, FF_DIM, 0, 0);
    transpose_quant_kernel<<<dim3(D_MODEL/32, FF_DIM/32, 1), blk>>>(
        w2, (h16*)w2T_, FF_DIM, D_MODEL, 0, 0);

    // 6. vT per batch: v = qkv cols 2048..3071 -> [1024, 2048] fp16
    transpose16_kernel<<<dim3(D_MODEL/32, SEQ/32, BATCH), blk>>>(
        qkv + 2*D_MODEL, (h16*)vT16_, SEQ, QKV_N,
        (long long)SEQ*QKV_N, (long long)D_MODEL*SEQ);

    // 7. scores = q @ k^T (fp32 out); q,k strided views of qkv
    gemm_nt<1,0,0,0><<<dim3(SEQ/BN, SEQ/BM, BATCH), blk, SMEM_TOTAL>>>(
        qkv, qkv + D_MODEL, nullptr, nullptr, (float*)sc_, nullptr,
        SEQ, SEQ, D_MODEL, QKV_N, QKV_N, SEQ,
        (long long)SEQ*QKV_N, (long long)SEQ*QKV_N, (long long)SEQ*SEQ);

    // 8. softmax -> fp16 P
    softmax_kernel<<<BATCH*SEQ, blk>>>((float*)sc_, (h16*)p16_);

    // 9. ctx = P @ vT^T (fp16 out)
    gemm_nt<0,1,0,0><<<dim3(D_MODEL/BN, SEQ/BM, BATCH), blk, SMEM_TOTAL>>>(
        (h16*)p16_, (h16*)vT16_, nullptr, nullptr, nullptr, (h16*)c16_,
        SEQ, D_MODEL, SEQ, SEQ, SEQ, D_MODEL,
        (long long)SEQ*SEQ, (long long)D_MODEL*SEQ, (long long)SEQ*D_MODEL);

    // 10. x1 = x + ctx @ wo^T + bo
    gemm_nt<1,0,0,1><<<dim3(D_MODEL/BN, M_TOT/BM, 1), blk, SMEM_TOTAL>>>(
        (h16*)c16_, (h16*)woT_, bo, x, (float*)x1_, nullptr,
        M_TOT, D_MODEL, D_MODEL, D_MODEL, D_MODEL, D_MODEL, 0, 0, 0);

    // 11. y1 = LN1(x1), emit fp16
    layernorm_kernel<true><<<M_TOT, blk>>>((float*)x1_, g1, beta1, (float*)y1_, (h16*)y116_);

    // 12. h = relu(y1 @ w1^T + b1) (fp16 out)
    gemm_nt<0,1,1,0><<<dim3(FF_DIM/BN, M_TOT/BM, 1), blk, SMEM_TOTAL>>>(
        (h16*)y116_, (h16*)w1T_, b1, nullptr, nullptr, (h16*)hh_,
        M_TOT, FF_DIM, D_MODEL, D_MODEL, D_MODEL, FF_DIM, 0, 0, 0);

    // 13. x2 = y1 + h @ w2^T + b2
    gemm_nt<1,0,0,1><<<dim3(D_MODEL/BN, M_TOT/BM, 1), blk, SMEM_TOTAL>>>(
        (h16*)hh_, (h16*)w2T_, b2, (float*)y1_, (float*)x2_, nullptr,
        M_TOT, D_MODEL, FF_DIM, FF_DIM, FF_DIM, D_MODEL, 0, 0, 0);

    // 14. out = LN2(x2)
    layernorm_kernel<false><<<M_TOT, blk>>>((float*)x2_, g2, beta2, out, nullptr);
}

// round 14
// speedup vs baseline: 1.7656x; 1.0208x over previous
#include <cuda_runtime.h>
#include <cuda_fp16.h>
#include <math.h>
#include <stdint.h>

// ---------------------------------------------------------------------------
// SmallTransformerBlock via mma.sync single-pass fp16 GEMMs (sm_103 PTX).
// R14: scores GEMM emits scaled fp16 (no fp32 round-trip), softmax is an
// in-place fp16 pass; cp.async split around B-ldsm. Rest = R13.
// ---------------------------------------------------------------------------

#define D_MODEL 1024
#define FF_DIM  4096
#define BATCH   4
#define SEQ     2048
#define M_TOT   (BATCH * SEQ)          // 8192
#define QKV_N   (3 * D_MODEL)          // 3072

#define BM 128
#define BN 128
#define BK 64
#define STAGES 3
#define ABUF_BYTES (128 * 128)
#define BBUF_BYTES (128 * 128)
#define STAGE_BYTES (ABUF_BYTES + BBUF_BYTES)  // 32768
#define SMEM_TOTAL  (STAGES * STAGE_BYTES)     // 98304

typedef __half h16;

// -------------------------- scratch (device globals) -----------------------
__device__ h16   g_x16   [M_TOT * D_MODEL];
__device__ h16   g_wqkvT [QKV_N * D_MODEL];
__device__ h16   g_woT   [D_MODEL * D_MODEL];
__device__ h16   g_w1T   [FF_DIM * D_MODEL];
__device__ h16   g_w2T   [D_MODEL * FF_DIM];
__device__ float g_bqkv  [QKV_N];
__device__ h16   g_qkv16 [M_TOT * QKV_N];
__device__ h16   g_vT16  [M_TOT * D_MODEL];    // [B][D, T]
__device__ h16   g_sh    [BATCH * SEQ * SEQ];  // scores fp16 -> softmax in place
__device__ h16   g_ctx16 [M_TOT * D_MODEL];
__device__ float g_x1    [M_TOT * D_MODEL];
__device__ float g_y1    [M_TOT * D_MODEL];
__device__ h16   g_y116  [M_TOT * D_MODEL];
__device__ h16   g_h16a  [M_TOT * FF_DIM];
__device__ float g_x2    [M_TOT * D_MODEL];

// ------------------------------- PTX helpers -------------------------------
__device__ __forceinline__ uint32_t smem_u32(const void* p) {
    uint32_t a;
    asm("{ .reg .u64 t; cvta.to.shared.u64 t, %1; cvt.u32.u64 %0, t; }"
        : "=r"(a) : "l"(p));
    return a;
}
__device__ __forceinline__ void cp16(uint32_t dst, const void* src) {
    asm volatile("cp.async.cg.shared.global [%0], [%1], 16;\n" :: "r"(dst), "l"(src));
}
__device__ __forceinline__ void cp_commit() {
    asm volatile("cp.async.commit_group;\n" ::: "memory");
}
template<int N> __device__ __forceinline__ void cp_wait() {
    asm volatile("cp.async.wait_group %0;\n" :: "n"(N) : "memory");
}
__device__ __forceinline__ void ldsm4(uint32_t& r0, uint32_t& r1, uint32_t& r2,
                                      uint32_t& r3, uint32_t addr) {
    asm volatile("ldmatrix.sync.aligned.m8n8.x4.shared.b16 {%0,%1,%2,%3}, [%4];\n"
                 : "=r"(r0), "=r"(r1), "=r"(r2), "=r"(r3) : "r"(addr));
}
__device__ __forceinline__ void mma16816(float* d, const uint32_t* a, const uint32_t* b) {
    asm volatile(
        "mma.sync.aligned.m16n8k16.row.col.f32.f16.f16.f32 "
        "{%0,%1,%2,%3}, {%4,%5,%6,%7}, {%8,%9}, {%0,%1,%2,%3};\n"
        : "+f"(d[0]), "+f"(d[1]), "+f"(d[2]), "+f"(d[3])
        : "r"(a[0]), "r"(a[1]), "r"(a[2]), "r"(a[3]), "r"(b[0]), "r"(b[1]));
}
__device__ __forceinline__ uint32_t pack2h(h16 a, h16 b) {
    return ((uint32_t)__half_as_ushort(b) << 16) | __half_as_ushort(a);
}

// ---------------------------------------------------------------------------
// GEMM NT fp16: C[M,N] = A16 @ B16^T (+bias)(relu)(+res), strided operands.
// oscale applied before HALFOUT pack (used to fold attention 1/scale).
// 128x128x64 tile, 8 warps, 3-stage pipeline, cp.async interleaved, occ 2.
// ---------------------------------------------------------------------------
template<bool F32OUT, bool HALFOUT, bool RELU, bool HASRES>
__global__ __launch_bounds__(256, 2) void gemm_nt(
    const h16* __restrict__ A16, const h16* __restrict__ B16,
    const float* __restrict__ bias, const float* __restrict__ Res,
    float* __restrict__ Cf, h16* __restrict__ Ch, float oscale,
    int M, int N, int K, int lda, int ldb, int ldc,
    long long aS, long long bS, long long cS)
{
    extern __shared__ char smraw[];
    const uint32_t smb = smem_u32(smraw);
    const int tid  = threadIdx.x;
    const int wid  = tid >> 5;
    const int lane = tid & 31;
    const int wm = wid & 3;
    const int wn = wid >> 2;
    const int quad = lane >> 3, lrow = lane & 7;
    const int bz = blockIdx.z;
    const int bm = blockIdx.y * BM;
    const int bn = blockIdx.x * BN;

    const int trow = tid >> 3;
    const int lc   = tid & 7;
    const int lk   = lc * 8;
    const long long rowStepA = 32LL * lda;
    const long long rowStepB = 32LL * ldb;
    const h16* pA = A16 + (long long)bz * aS + (long long)(bm + trow) * lda + lk;
    const h16* pB = B16 + (long long)bz * bS + (long long)(bn + trow) * ldb + lk;
    const uint32_t d0 = (uint32_t)(trow * 128 + ((lc ^ (trow & 7)) * 16));

    const uint32_t bit4  = (uint32_t)(((quad >> 1) ^ (lrow & 1)) << 4);
    const uint32_t lrow6 = (uint32_t)(lrow & 6);
    uint32_t baseA[2], baseB[4];
    #pragma unroll
    for (int fm = 0; fm < 2; fm++)
        baseA[fm] = (uint32_t)((wm * 32 + fm * 16 + (quad & 1) * 8 + lrow) * 128) + bit4;
    #pragma unroll
    for (int f2 = 0; f2 < 4; f2++)
        baseB[f2] = ABUF_BYTES +
            (uint32_t)((wn * 64 + f2 * 16 + (quad & 1) * 8 + lrow) * 128) + bit4;

    float acc[2][8][4];
    #pragma unroll
    for (int i = 0; i < 2; i++)
        #pragma unroll
        for (int j = 0; j < 8; j++)
            #pragma unroll
            for (int c = 0; c < 4; c++) acc[i][j][c] = 0.0f;

    const int T = K / BK;

    auto cp_one = [&](int idx, int k0, uint32_t stb) {
        if (idx < 4)
            cp16(stb + d0 + (uint32_t)idx * 4096, pA + (long long)idx * rowStepA + k0);
        else
            cp16(stb + ABUF_BYTES + d0 + (uint32_t)(idx - 4) * 4096,
                 pB + (long long)(idx - 4) * rowStepB + k0);
    };
    auto load_stage = [&](int kt, int s) {
        const uint32_t stb = smb + (uint32_t)s * STAGE_BYTES;
        const int k0 = kt * BK;
        #pragma unroll
        for (int i = 0; i < 8; i++) cp_one(i, k0, stb);
    };

    load_stage(0, 0); cp_commit();
    load_stage(1, 1); cp_commit();

    int sCur = 0, sLd = 2;
    for (int t = 0; t < T; t++) {
        cp_wait<1>();
        __syncthreads();
        const uint32_t stb  = smb + (uint32_t)sCur * STAGE_BYTES;
        const uint32_t stbL = smb + (uint32_t)sLd * STAGE_BYTES;
        const bool doLoad = (t + 2 < T);
        const int k0n = (t + 2) * BK;

        #pragma unroll
        for (int ks = 0; ks < 4; ks++) {
            const uint32_t kk = ((uint32_t)(ks * 2) ^ lrow6) << 4;
            if (doLoad) cp_one(ks * 2, k0n, stbL);
            uint32_t ah[2][4];
            #pragma unroll
            for (int fm = 0; fm < 2; fm++)
                ldsm4(ah[fm][0], ah[fm][1], ah[fm][2], ah[fm][3],
                      stb + baseA[fm] + kk);
            uint32_t bf[8][2];
            #pragma unroll
            for (int f2 = 0; f2 < 4; f2++) {
                uint32_t t0, t1, t2, t3;
                ldsm4(t0, t1, t2, t3, stb + baseB[f2] + kk);
                bf[2*f2][0] = t0; bf[2*f2][1] = t2;
                bf[2*f2+1][0] = t1; bf[2*f2+1][1] = t3;
            }
            if (doLoad) cp_one(ks * 2 + 1, k0n, stbL);
            #pragma unroll
            for (int fm = 0; fm < 2; fm++)
                #pragma unroll
                for (int fn = 0; fn < 8; fn++)
                    mma16816(acc[fm][fn], ah[fm], bf[fn]);
        }
        cp_commit();
        sCur = (sCur == 2) ? 0 : sCur + 1;
        sLd  = (sLd  == 2) ? 0 : sLd  + 1;
    }

    // ---------------- epilogue ----------------
    const int groupID = lane >> 2, tIdx = lane & 3;
    #pragma unroll
    for (int fm = 0; fm < 2; fm++) {
        #pragma unroll
        for (int half = 0; half < 2; half++) {
            int row = bm + wm * 32 + fm * 16 + half * 8 + groupID;
            long long rbase = (long long)bz * cS + (long long)row * ldc;
            #pragma unroll
            for (int fn = 0; fn < 8; fn++) {
                int col = bn + wn * 64 + fn * 8 + tIdx * 2;
                float v0 = acc[fm][fn][half * 2 + 0];
                float v1 = acc[fm][fn][half * 2 + 1];
                if (bias) { v0 += __ldg(bias + col); v1 += __ldg(bias + col + 1); }
                if (RELU) { v0 = fmaxf(v0, 0.0f); v1 = fmaxf(v1, 0.0f); }
                if (HASRES) {
                    float2 rv = *(const float2*)(Res + rbase + col);
                    v0 += rv.x; v1 += rv.y;
                }
                if (F32OUT)
                    *(float2*)(Cf + rbase + col) = make_float2(v0, v1);
                if (HALFOUT) {
                    v0 *= oscale; v1 *= oscale;
                    *(uint32_t*)(Ch + rbase + col) =
                        pack2h(__float2half_rn(v0), __float2half_rn(v1));
                }
            }
        }
    }
}

// ---------------------------------------------------------------------------
// Elementwise quantize: fp32 -> fp16
// ---------------------------------------------------------------------------
__global__ __launch_bounds__(256) void quant_kernel(
    const float* __restrict__ src, h16* __restrict__ dst, int n4)
{
    int i = blockIdx.x * 256 + threadIdx.x;
    if (i >= n4) return;
    float4 v = ((const float4*)src)[i];
    ((uint2*)dst)[i] = make_uint2(
        pack2h(__float2half_rn(v.x), __float2half_rn(v.y)),
        pack2h(__float2half_rn(v.z), __float2half_rn(v.w)));
}

// bias concat: [bq | bk | bv]
__global__ __launch_bounds__(256) void bias_concat_kernel(
    const float* __restrict__ bq, const float* __restrict__ bk,
    const float* __restrict__ bv, float* __restrict__ dst)
{
    int i = blockIdx.x * 256 + threadIdx.x;
    if (i >= QKV_N) return;
    float v = (i < D_MODEL) ? bq[i]
            : (i < 2 * D_MODEL) ? bk[i - D_MODEL] : bv[i - 2 * D_MODEL];
    dst[i] = v;
}

// ---------------------------------------------------------------------------
// Transpose-quantize: src [R,C] fp32 -> dst [C,R] fp16.
// ---------------------------------------------------------------------------
__global__ __launch_bounds__(256) void transpose_quant_kernel(
    const float* __restrict__ src, h16* __restrict__ dstT,
    int R, int C, long long sS, long long dS)
{
    __shared__ float tile[32][33];
    const float* S = src + (long long)blockIdx.z * sS;
    int c0 = blockIdx.x * 32, r0 = blockIdx.y * 32;
    int tx = threadIdx.x & 31, ty = threadIdx.x >> 5;
    #pragma unroll
    for (int i = 0; i < 32; i += 8)
        tile[ty + i][tx] = S[(long long)(r0 + ty + i) * C + c0 + tx];
    __syncthreads();
    #pragma unroll
    for (int i = 0; i < 32; i += 8) {
        long long o = (long long)blockIdx.z * dS + (long long)(c0 + ty + i) * R + r0 + tx;
        dstT[o] = __float2half_rn(tile[tx][ty + i]);
    }
}

// fp16 strided transpose: src [R rows, stride ldS] -> dst [C, R]
__global__ __launch_bounds__(256) void transpose16_kernel(
    const h16* __restrict__ src, h16* __restrict__ dstT,
    int R, int ldS, long long sS, long long dS)
{
    __shared__ h16 tile[32][33];
    const h16* S = src + (long long)blockIdx.z * sS;
    int c0 = blockIdx.x * 32, r0 = blockIdx.y * 32;
    int tx = threadIdx.x & 31, ty = threadIdx.x >> 5;
    #pragma unroll
    for (int i = 0; i < 32; i += 8)
        tile[ty + i][tx] = S[(long long)(r0 + ty + i) * ldS + c0 + tx];
    __syncthreads();
    #pragma unroll
    for (int i = 0; i < 32; i += 8) {
        long long o = (long long)blockIdx.z * dS + (long long)(c0 + ty + i) * R + r0 + tx;
        dstT[o] = tile[tx][ty + i];
    }
}

// Batched: the four 1024x1024 weights in one launch.
__global__ __launch_bounds__(256) void transpose_quant4_kernel(
    const float* __restrict__ s0, const float* __restrict__ s1,
    const float* __restrict__ s2, const float* __restrict__ s3,
    h16* __restrict__ d0p, h16* __restrict__ d1p,
    h16* __restrict__ d2p, h16* __restrict__ d3p)
{
    __shared__ float tile[32][33];
    const int z = blockIdx.z;
    const float* S = (z == 0) ? s0 : (z == 1) ? s1 : (z == 2) ? s2 : s3;
    h16* D = (z == 0) ? d0p : (z == 1) ? d1p : (z == 2) ? d2p : d3p;
    int c0 = blockIdx.x * 32, r0 = blockIdx.y * 32;
    int tx = threadIdx.x & 31, ty = threadIdx.x >> 5;
    #pragma unroll
    for (int i = 0; i < 32; i += 8)
        tile[ty + i][tx] = S[(long long)(r0 + ty + i) * D_MODEL + c0 + tx];
    __syncthreads();
    #pragma unroll
    for (int i = 0; i < 32; i += 8) {
        long long o = (long long)(c0 + ty + i) * D_MODEL + r0 + tx;
        D[o] = __float2half_rn(tile[tx][ty + i]);
    }
}

// ------------------------------- reductions --------------------------------
__device__ __forceinline__ float block_sum(float v) {
    __shared__ float sh[8];
    int lane = threadIdx.x & 31, w = threadIdx.x >> 5;
    #pragma unroll
    for (int o = 16; o > 0; o >>= 1) v += __shfl_xor_sync(0xffffffffu, v, o);
    if (lane == 0) sh[w] = v;
    __syncthreads();
    if (w == 0) {
        float t = (lane < 8) ? sh[lane] : 0.0f;
        #pragma unroll
        for (int o = 4; o > 0; o >>= 1) t += __shfl_xor_sync(0xffffffffu, t, o);
        if (lane == 0) sh[0] = t;
    }
    __syncthreads();
    float r = sh[0];
    __syncthreads();
    return r;
}
__device__ __forceinline__ float block_max(float v) {
    __shared__ float sh[8];
    int lane = threadIdx.x & 31, w = threadIdx.x >> 5;
    #pragma unroll
    for (int o = 16; o > 0; o >>= 1) v = fmaxf(v, __shfl_xor_sync(0xffffffffu, v, o));
    if (lane == 0) sh[w] = v;
    __syncthreads();
    if (w == 0) {
        float t = (lane < 8) ? sh[lane] : -3.4e38f;
        #pragma unroll
        for (int o = 4; o > 0; o >>= 1) t = fmaxf(t, __shfl_xor_sync(0xffffffffu, t, o));
        if (lane == 0) sh[0] = t;
    }
    __syncthreads();
    float r = sh[0];
    __syncthreads();
    return r;
}

// ---------------------------------------------------------------------------
// In-place fp16 softmax over rows of SEQ=2048 (scores already scaled).
// One uint4 (8 halves) per thread.
// ---------------------------------------------------------------------------
__global__ __launch_bounds__(256) void softmax16_kernel(h16* __restrict__ S)
{
    h16* row = S + (long long)blockIdx.x * SEQ;
    int tid = threadIdx.x;
    uint4 raw = ((const uint4*)row)[tid];
    float2 f0 = __half22float2(*(__half2*)&raw.x);
    float2 f1 = __half22float2(*(__half2*)&raw.y);
    float2 f2 = __half22float2(*(__half2*)&raw.z);
    float2 f3 = __half22float2(*(__half2*)&raw.w);

    float m = fmaxf(fmaxf(fmaxf(f0.x, f0.y), fmaxf(f1.x, f1.y)),
                    fmaxf(fmaxf(f2.x, f2.y), fmaxf(f3.x, f3.y)));
    m = block_max(m);
    f0.x = expf(f0.x - m); f0.y = expf(f0.y - m);
    f1.x = expf(f1.x - m); f1.y = expf(f1.y - m);
    f2.x = expf(f2.x - m); f2.y = expf(f2.y - m);
    f3.x = expf(f3.x - m); f3.y = expf(f3.y - m);
    float s = f0.x + f0.y + f1.x + f1.y + f2.x + f2.y + f3.x + f3.y;
    s = block_sum(s);
    float inv = 1.0f / s;

    uint4 outw;
    outw.x = pack2h(__float2half_rn(f0.x * inv), __float2half_rn(f0.y * inv));
    outw.y = pack2h(__float2half_rn(f1.x * inv), __float2half_rn(f1.y * inv));
    outw.z = pack2h(__float2half_rn(f2.x * inv), __float2half_rn(f2.y * inv));
    outw.w = pack2h(__float2half_rn(f3.x * inv), __float2half_rn(f3.y * inv));
    ((uint4*)row)[tid] = outw;
}

// ---------------------------------------------------------------------------
// LayerNorm D=1024; optional fp16 quantized emission.
// ---------------------------------------------------------------------------
template<bool EMITH>
__global__ __launch_bounds__(256) void layernorm_kernel(
    const float* __restrict__ X, const float* __restrict__ g,
    const float* __restrict__ b, float* __restrict__ Y, h16* __restrict__ Yh)
{
    const float* x = X + (long long)blockIdx.x * D_MODEL;
    int tid = threadIdx.x;
    float4 v = ((const float4*)x)[tid];
    float s = v.x + v.y + v.z + v.w;
    s = block_sum(s);
    float mean = s * (1.0f / D_MODEL);
    float dx=v.x-mean, dy=v.y-mean, dz=v.z-mean, dw=v.w-mean;
    float ss = dx*dx + dy*dy + dz*dz + dw*dw;
    ss = block_sum(ss);
    float rstd = rsqrtf(ss * (1.0f / D_MODEL) + 1e-5f);
    float4 gg = ((const float4*)g)[tid];
    float4 bb = ((const float4*)b)[tid];
    float4 o;
    o.x = dx*rstd*gg.x + bb.x;
    o.y = dy*rstd*gg.y + bb.y;
    o.z = dz*rstd*gg.z + bb.z;
    o.w = dw*rstd*gg.w + bb.w;
    long long base = (long long)blockIdx.x * D_MODEL;
    ((float4*)(Y + base))[tid] = o;
    if (EMITH) {
        ((uint2*)(Yh + base))[tid] = make_uint2(
            pack2h(__float2half_rn(o.x), __float2half_rn(o.y)),
            pack2h(__float2half_rn(o.z), __float2half_rn(o.w)));
    }
}

// ---------------------------------------------------------------------------
// Launch
// ---------------------------------------------------------------------------
extern "C" void kernel_launch(void* const* d_in, const int* in_sizes, int n_in,
                              void* d_out, int out_size)
{
    const float* x     = (const float*)d_in[0];
    const float* wq    = (const float*)d_in[1];
    const float* bq    = (const float*)d_in[2];
    const float* wk    = (const float*)d_in[3];
    const float* bk    = (const float*)d_in[4];
    const float* wv    = (const float*)d_in[5];
    const float* bv    = (const float*)d_in[6];
    const float* wo    = (const float*)d_in[7];
    const float* bo    = (const float*)d_in[8];
    const float* w1    = (const float*)d_in[9];
    const float* b1    = (const float*)d_in[10];
    const float* w2    = (const float*)d_in[11];
    const float* b2    = (const float*)d_in[12];
    const float* g1    = (const float*)d_in[13];
    const float* beta1 = (const float*)d_in[14];
    const float* g2    = (const float*)d_in[15];
    const float* beta2 = (const float*)d_in[16];
    float* out = (float*)d_out;

    #define SYM(p, s) void* p##_; cudaGetSymbolAddress(&p##_, s);
    SYM(x16, g_x16)
    SYM(wqkvT, g_wqkvT) SYM(woT, g_woT)
    SYM(w1T, g_w1T) SYM(w2T, g_w2T)
    SYM(bqkv, g_bqkv)
    SYM(qkv16, g_qkv16)
    SYM(vT16, g_vT16)
    SYM(sh, g_sh)
    SYM(c16, g_ctx16)
    SYM(x1, g_x1)   SYM(y1, g_y1)  SYM(y116, g_y116)
    SYM(hh, g_h16a)
    SYM(x2, g_x2)
    #undef SYM

    cudaFuncSetAttribute(gemm_nt<1,0,0,0>, cudaFuncAttributeMaxDynamicSharedMemorySize, SMEM_TOTAL);
    cudaFuncSetAttribute(gemm_nt<0,1,0,0>, cudaFuncAttributeMaxDynamicSharedMemorySize, SMEM_TOTAL);
    cudaFuncSetAttribute(gemm_nt<0,1,1,0>, cudaFuncAttributeMaxDynamicSharedMemorySize, SMEM_TOTAL);
    cudaFuncSetAttribute(gemm_nt<1,0,0,1>, cudaFuncAttributeMaxDynamicSharedMemorySize, SMEM_TOTAL);

    dim3 blk(256);
    h16* qkv = (h16*)qkv16_;
    const float inv_scale = 0.0883883476483184f;  // 1/sqrt(128)

    // 0. quantize x -> fp16
    quant_kernel<<<M_TOT * D_MODEL / 4 / 256, blk>>>(x, (h16*)x16_, M_TOT * D_MODEL / 4);

    // 1. transpose-quantize wq,wk,wv into wqkvT; wo into woT
    transpose_quant4_kernel<<<dim3(D_MODEL/32, D_MODEL/32, 4), blk>>>(
        wq, wk, wv, wo,
        (h16*)wqkvT_, (h16*)wqkvT_ + D_MODEL*D_MODEL,
        (h16*)wqkvT_ + 2*D_MODEL*D_MODEL, (h16*)woT_);

    // 2. concat biases
    bias_concat_kernel<<<(QKV_N + 255)/256, blk>>>(bq, bk, bv, (float*)bqkv_);

    // 3. fused QKV GEMM -> qkv16 [8192,3072]
    gemm_nt<0,1,0,0><<<dim3(QKV_N/BN, M_TOT/BM, 1), blk, SMEM_TOTAL>>>(
        (h16*)x16_, (h16*)wqkvT_, (float*)bqkv_, nullptr, nullptr, qkv, 1.0f,
        M_TOT, QKV_N, D_MODEL, D_MODEL, D_MODEL, QKV_N, 0, 0, 0);

    // 4-5. w1, w2 transposes
    transpose_quant_kernel<<<dim3(FF_DIM/32, D_MODEL/32, 1), blk>>>(
        w1, (h16*)w1T_, D_MODEL, FF_DIM, 0, 0);
    transpose_quant_kernel<<<dim3(D_MODEL/32, FF_DIM/32, 1), blk>>>(
        w2, (h16*)w2T_, FF_DIM, D_MODEL, 0, 0);

    // 6. vT per batch
    transpose16_kernel<<<dim3(D_MODEL/32, SEQ/32, BATCH), blk>>>(
        qkv + 2*D_MODEL, (h16*)vT16_, SEQ, QKV_N,
        (long long)SEQ*QKV_N, (long long)D_MODEL*SEQ);

    // 7. scores = (q @ k^T) * inv_scale, fp16 out
    gemm_nt<0,1,0,0><<<dim3(SEQ/BN, SEQ/BM, BATCH), blk, SMEM_TOTAL>>>(
        qkv, qkv + D_MODEL, nullptr, nullptr, nullptr, (h16*)sh_, inv_scale,
        SEQ, SEQ, D_MODEL, QKV_N, QKV_N, SEQ,
        (long long)SEQ*QKV_N, (long long)SEQ*QKV_N, (long long)SEQ*SEQ);

    // 8. softmax in place (fp16)
    softmax16_kernel<<<BATCH*SEQ, blk>>>((h16*)sh_);

    // 9. ctx = P @ vT^T (fp16 out)
    gemm_nt<0,1,0,0><<<dim3(D_MODEL/BN, SEQ/BM, BATCH), blk, SMEM_TOTAL>>>(
        (h16*)sh_, (h16*)vT16_, nullptr, nullptr, nullptr, (h16*)c16_, 1.0f,
        SEQ, D_MODEL, SEQ, SEQ, SEQ, D_MODEL,
        (long long)SEQ*SEQ, (long long)D_MODEL*SEQ, (long long)SEQ*D_MODEL);

    // 10. x1 = x + ctx @ wo^T + bo
    gemm_nt<1,0,0,1><<<dim3(D_MODEL/BN, M_TOT/BM, 1), blk, SMEM_TOTAL>>>(
        (h16*)c16_, (h16*)woT_, bo, x, (float*)x1_, nullptr, 1.0f,
        M_TOT, D_MODEL, D_MODEL, D_MODEL, D_MODEL, D_MODEL, 0, 0, 0);

    // 11. y1 = LN1(x1), emit fp16
    layernorm_kernel<true><<<M_TOT, blk>>>((float*)x1_, g1, beta1, (float*)y1_, (h16*)y116_);

    // 12. h = relu(y1 @ w1^T + b1) (fp16 out)
    gemm_nt<0,1,1,0><<<dim3(FF_DIM/BN, M_TOT/BM, 1), blk, SMEM_TOTAL>>>(
        (h16*)y116_, (h16*)w1T_, b1, nullptr, nullptr, (h16*)hh_, 1.0f,
        M_TOT, FF_DIM, D_MODEL, D_MODEL, D_MODEL, FF_DIM, 0, 0, 0);

    // 13. x2 = y1 + h @ w2^T + b2
    gemm_nt<1,0,0,1><<<dim3(D_MODEL/BN, M_TOT/BM, 1), blk, SMEM_TOTAL>>>(
        (h16*)hh_, (h16*)w2T_, b2, (float*)y1_, (float*)x2_, nullptr, 1.0f,
        M_TOT, D_MODEL, FF_DIM, FF_DIM, FF_DIM, D_MODEL, 0, 0, 0);

    // 14. out = LN2(x2)
    layernorm_kernel<false><<<M_TOT, blk>>>((float*)x2_, g2, beta2, out, nullptr);
}